// round 6
// baseline (speedup 1.0000x reference)
#include <cuda_runtime.h>
#include <mma.h>
#include <cstdint>

using namespace nvcuda;

#define NODES_MAX 50000
#define PAD_M     50176      // 392*128, pad for unguarded wmma stores
#define E_MAX     1000000
#define IN_C  256
#define HID_C 128
#define OUT_C 64

#define SCAN_B    196        // scan blocks: 196*256 = 50176 >= NODES_MAX

// ---------------- scratch ----------------------------------------------------
__device__ float g_f1[PAD_M * HID_C];        // gemm1 raw output (X@W1)
__device__ float g_a1[NODES_MAX * HID_C];    // layer-1 aggregated (pre-bias/relu)
__device__ float g_f2[PAD_M * OUT_C];        // gemm2 raw output
__device__ float g_dinv[NODES_MAX];
__device__ int   g_deg [NODES_MAX];
__device__ int   g_row_start[NODES_MAX + 1];
__device__ int   g_cursor[NODES_MAX];
__device__ int   g_src[E_MAX];               // CSR-by-dst: source node per slot
__device__ int   g_bsum[SCAN_B];             // per-block deg sums
__device__ int   g_boff[SCAN_B];             // exclusive scan of g_bsum
__device__ int   g_is64;

// ---------------- prep: zero deg + dtype detect ------------------------------
__global__ void prep_kernel(const long long* __restrict__ p, int E, int M) {
    int i = blockIdx.x * blockDim.x + threadIdx.x;
    if (i < M) g_deg[i] = 0;
    if (blockIdx.x == 0) {
        __shared__ int bad;
        if (threadIdx.x == 0) bad = 0;
        __syncthreads();
        if ((int)threadIdx.x < 256 && (int)threadIdx.x < E) {
            long long v = p[threadIdx.x];
            if (v < 0 || v >= (long long)M) bad = 1;
        }
        __syncthreads();
        if (threadIdx.x == 0) g_is64 = bad ? 0 : 1;
    }
}

__device__ __forceinline__ void get_edge(const void* ei, int e, int E, int is64,
                                         int& s, int& d) {
    if (is64) {
        const long long* p = (const long long*)ei;
        s = (int)p[e]; d = (int)p[E + e];
    } else {
        const int* p = (const int*)ei;
        s = p[e]; d = p[E + e];
    }
}

__global__ void count_deg_kernel(const void* __restrict__ ei, int E) {
    int e = blockIdx.x * blockDim.x + threadIdx.x;
    if (e >= E) return;
    int s, d;
    get_edge(ei, e, E, g_is64, s, d);
    atomicAdd(&g_deg[d], 1);
}

// ---------------- hierarchical scan -----------------------------------------
// scan1: per-block reduce of deg -> g_bsum; also dinv = rsqrt(deg+1)
__global__ __launch_bounds__(256) void scan1_kernel(int M) {
    __shared__ int red[8];
    int i = blockIdx.x * 256 + threadIdx.x;
    int d = (i < M) ? g_deg[i] : 0;
    if (i < M) g_dinv[i] = rsqrtf((float)(d + 1));
    int v = d;
    #pragma unroll
    for (int off = 16; off > 0; off >>= 1) v += __shfl_down_sync(0xffffffffu, v, off);
    if ((threadIdx.x & 31) == 0) red[threadIdx.x >> 5] = v;
    __syncthreads();
    if (threadIdx.x < 8) {
        int s = red[threadIdx.x];
        #pragma unroll
        for (int off = 4; off > 0; off >>= 1) s += __shfl_down_sync(0xffu, s, off);
        if (threadIdx.x == 0) g_bsum[blockIdx.x] = s;
    }
}

// scan2: exclusive scan of SCAN_B block sums (1 block, 256 threads)
__global__ __launch_bounds__(256) void scan2_kernel() {
    __shared__ int sm[256];
    int t = threadIdx.x;
    sm[t] = (t < SCAN_B) ? g_bsum[t] : 0;
    __syncthreads();
    #pragma unroll
    for (int off = 1; off < 256; off <<= 1) {
        int v = (t >= off) ? sm[t - off] : 0;
        __syncthreads();
        sm[t] += v;
        __syncthreads();
    }
    if (t < SCAN_B) g_boff[t] = (t > 0) ? sm[t - 1] : 0;   // exclusive
}

// scan3: block-local exclusive scan + block offset -> row_start, cursor
__global__ __launch_bounds__(256) void scan3_kernel(int M, int E) {
    __shared__ int sm[256];
    int t = threadIdx.x;
    int i = blockIdx.x * 256 + t;
    int d = (i < M) ? g_deg[i] : 0;
    sm[t] = d;
    __syncthreads();
    #pragma unroll
    for (int off = 1; off < 256; off <<= 1) {
        int v = (t >= off) ? sm[t - off] : 0;
        __syncthreads();
        sm[t] += v;
        __syncthreads();
    }
    if (i < M) {
        int rs = g_boff[blockIdx.x] + sm[t] - d;    // exclusive prefix
        g_row_start[i] = rs;
        g_cursor[i]    = rs;
    }
    if (i == M - 1 || (blockIdx.x == 0 && t == 0 && M == 0))
        g_row_start[M] = E;
}

__global__ void fill_kernel(const void* __restrict__ ei, int E) {
    int e = blockIdx.x * blockDim.x + threadIdx.x;
    if (e >= E) return;
    int s, d;
    get_edge(ei, e, E, g_is64, s, d);
    int pos = atomicAdd(&g_cursor[d], 1);
    g_src[pos] = s;
}

// ---------------- GEMM1 (TF32 wmma): g_f1 = X @ W1 (raw) --------------------
__global__ __launch_bounds__(256, 2) void gemm1_kernel(
    const float* __restrict__ A, const float* __restrict__ W, int M) {
    __shared__ float As[128][40];
    __shared__ float Bs[32][136];
    int tid = threadIdx.x;
    int wid = tid >> 5;
    int wm = wid & 3;
    int wn = wid >> 2;
    int bm = blockIdx.x * 128;

    wmma::fragment<wmma::accumulator, 16, 16, 8, float> c[2][4];
    #pragma unroll
    for (int i = 0; i < 2; i++)
        #pragma unroll
        for (int j = 0; j < 4; j++) wmma::fill_fragment(c[i][j], 0.f);

    for (int k0 = 0; k0 < IN_C; k0 += 32) {
        #pragma unroll
        for (int i = 0; i < 4; ++i) {
            int idx = tid * 4 + i;
            int r = idx >> 3, c4 = (idx & 7) * 4;
            int gm = bm + r;
            float4 v = make_float4(0.f, 0.f, 0.f, 0.f);
            if (gm < M) v = *(const float4*)&A[(size_t)gm * IN_C + k0 + c4];
            v.x = wmma::__float_to_tf32(v.x); v.y = wmma::__float_to_tf32(v.y);
            v.z = wmma::__float_to_tf32(v.z); v.w = wmma::__float_to_tf32(v.w);
            *(float4*)&As[r][c4] = v;
        }
        #pragma unroll
        for (int i = 0; i < 4; ++i) {
            int idx = tid * 4 + i;
            int kk = idx >> 5, n4 = (idx & 31) * 4;
            float4 v = *(const float4*)&W[(size_t)(k0 + kk) * HID_C + n4];
            v.x = wmma::__float_to_tf32(v.x); v.y = wmma::__float_to_tf32(v.y);
            v.z = wmma::__float_to_tf32(v.z); v.w = wmma::__float_to_tf32(v.w);
            *(float4*)&Bs[kk][n4] = v;
        }
        __syncthreads();
        #pragma unroll
        for (int ks = 0; ks < 32; ks += 8) {
            wmma::fragment<wmma::matrix_a, 16, 16, 8, wmma::precision::tf32, wmma::row_major> a[2];
            wmma::fragment<wmma::matrix_b, 16, 16, 8, wmma::precision::tf32, wmma::row_major> b[4];
            #pragma unroll
            for (int i = 0; i < 2; i++)
                wmma::load_matrix_sync(a[i], &As[wm * 32 + i * 16][ks], 40);
            #pragma unroll
            for (int j = 0; j < 4; j++)
                wmma::load_matrix_sync(b[j], &Bs[ks][wn * 64 + j * 16], 136);
            #pragma unroll
            for (int i = 0; i < 2; i++)
                #pragma unroll
                for (int j = 0; j < 4; j++)
                    wmma::mma_sync(c[i][j], a[i], b[j], c[i][j]);
        }
        __syncthreads();
    }
    #pragma unroll
    for (int i = 0; i < 2; i++)
        #pragma unroll
        for (int j = 0; j < 4; j++) {
            size_t off = (size_t)(bm + wm * 32 + i * 16) * HID_C + wn * 64 + j * 16;
            wmma::store_matrix_sync(&g_f1[off], c[i][j], HID_C, wmma::mem_row_major);
        }
}

// ---------------- gather layer 1 (warp per node) ----------------------------
__global__ __launch_bounds__(256) void gather1_kernel(int M) {
    int w    = (blockIdx.x * blockDim.x + threadIdx.x) >> 5;
    int lane = threadIdx.x & 31;
    if (w >= M) return;
    int start = g_row_start[w];
    int end   = g_row_start[w + 1];
    float dn = g_dinv[w];
    float4 acc = __ldg((const float4*)&g_f1[(size_t)w * HID_C] + lane);
    acc.x *= dn; acc.y *= dn; acc.z *= dn; acc.w *= dn;

    int i = start;
    for (; i + 4 <= end; i += 4) {
        int s0 = g_src[i], s1 = g_src[i + 1], s2 = g_src[i + 2], s3 = g_src[i + 3];
        float d0 = g_dinv[s0], d1 = g_dinv[s1], d2 = g_dinv[s2], d3 = g_dinv[s3];
        float4 v0 = __ldg((const float4*)&g_f1[(size_t)s0 * HID_C] + lane);
        float4 v1 = __ldg((const float4*)&g_f1[(size_t)s1 * HID_C] + lane);
        float4 v2 = __ldg((const float4*)&g_f1[(size_t)s2 * HID_C] + lane);
        float4 v3 = __ldg((const float4*)&g_f1[(size_t)s3 * HID_C] + lane);
        acc.x += v0.x * d0 + v1.x * d1 + v2.x * d2 + v3.x * d3;
        acc.y += v0.y * d0 + v1.y * d1 + v2.y * d2 + v3.y * d3;
        acc.z += v0.z * d0 + v1.z * d1 + v2.z * d2 + v3.z * d3;
        acc.w += v0.w * d0 + v1.w * d1 + v2.w * d2 + v3.w * d3;
    }
    for (; i < end; ++i) {
        int s = g_src[i];
        float ds = g_dinv[s];
        float4 v = __ldg((const float4*)&g_f1[(size_t)s * HID_C] + lane);
        acc.x += v.x * ds; acc.y += v.y * ds; acc.z += v.z * ds; acc.w += v.w * ds;
    }
    acc.x *= dn; acc.y *= dn; acc.z *= dn; acc.w *= dn;
    *((float4*)&g_a1[(size_t)w * HID_C] + lane) = acc;
}

// ---------------- GEMM2 (TF32 wmma): g_f2 = relu(a1 + b1) @ W2 (raw) --------
__global__ __launch_bounds__(256, 2) void gemm2_kernel(
    const float* __restrict__ W, const float* __restrict__ b1, int M) {
    __shared__ float As[128][40];
    __shared__ float Bs[32][72];
    __shared__ float b1s[HID_C];
    int tid = threadIdx.x;
    int wid = tid >> 5;
    int wm = wid & 3;
    int wn = wid >> 2;
    int bm = blockIdx.x * 128;
    if (tid < HID_C / 4) ((float4*)b1s)[tid] = ((const float4*)b1)[tid];
    __syncthreads();

    wmma::fragment<wmma::accumulator, 16, 16, 8, float> c[2][2];
    #pragma unroll
    for (int i = 0; i < 2; i++)
        #pragma unroll
        for (int j = 0; j < 2; j++) wmma::fill_fragment(c[i][j], 0.f);

    for (int k0 = 0; k0 < HID_C; k0 += 32) {
        #pragma unroll
        for (int i = 0; i < 4; ++i) {
            int idx = tid * 4 + i;
            int r = idx >> 3, c4 = (idx & 7) * 4;
            int gm = bm + r;
            float4 v = make_float4(0.f, 0.f, 0.f, 0.f);
            if (gm < M) {
                v = *(const float4*)&g_a1[(size_t)gm * HID_C + k0 + c4];
                v.x = fmaxf(v.x + b1s[k0 + c4 + 0], 0.f);
                v.y = fmaxf(v.y + b1s[k0 + c4 + 1], 0.f);
                v.z = fmaxf(v.z + b1s[k0 + c4 + 2], 0.f);
                v.w = fmaxf(v.w + b1s[k0 + c4 + 3], 0.f);
                v.x = wmma::__float_to_tf32(v.x); v.y = wmma::__float_to_tf32(v.y);
                v.z = wmma::__float_to_tf32(v.z); v.w = wmma::__float_to_tf32(v.w);
            }
            *(float4*)&As[r][c4] = v;
        }
        #pragma unroll
        for (int i = 0; i < 2; ++i) {
            int idx = tid * 2 + i;
            int kk = idx >> 4, n4 = (idx & 15) * 4;
            float4 v = *(const float4*)&W[(size_t)(k0 + kk) * OUT_C + n4];
            v.x = wmma::__float_to_tf32(v.x); v.y = wmma::__float_to_tf32(v.y);
            v.z = wmma::__float_to_tf32(v.z); v.w = wmma::__float_to_tf32(v.w);
            *(float4*)&Bs[kk][n4] = v;
        }
        __syncthreads();
        #pragma unroll
        for (int ks = 0; ks < 32; ks += 8) {
            wmma::fragment<wmma::matrix_a, 16, 16, 8, wmma::precision::tf32, wmma::row_major> a[2];
            wmma::fragment<wmma::matrix_b, 16, 16, 8, wmma::precision::tf32, wmma::row_major> b[2];
            #pragma unroll
            for (int i = 0; i < 2; i++)
                wmma::load_matrix_sync(a[i], &As[wm * 32 + i * 16][ks], 40);
            #pragma unroll
            for (int j = 0; j < 2; j++)
                wmma::load_matrix_sync(b[j], &Bs[ks][wn * 32 + j * 16], 72);
            #pragma unroll
            for (int i = 0; i < 2; i++)
                #pragma unroll
                for (int j = 0; j < 2; j++)
                    wmma::mma_sync(c[i][j], a[i], b[j], c[i][j]);
        }
        __syncthreads();
    }
    #pragma unroll
    for (int i = 0; i < 2; i++)
        #pragma unroll
        for (int j = 0; j < 2; j++) {
            size_t off = (size_t)(bm + wm * 32 + i * 16) * OUT_C + wn * 32 + j * 16;
            wmma::store_matrix_sync(&g_f2[off], c[i][j], OUT_C, wmma::mem_row_major);
        }
}

// ---------------- gather layer 2 + bias (16 lanes per node) -----------------
__global__ __launch_bounds__(256) void gather2_kernel(
    float* __restrict__ out, const float* __restrict__ b2, int M) {
    int t    = blockIdx.x * blockDim.x + threadIdx.x;
    int n    = t >> 4;
    int lane = t & 15;
    if (n >= M) return;
    int start = g_row_start[n];
    int end   = g_row_start[n + 1];
    float dn = g_dinv[n];
    float4 acc = __ldg((const float4*)&g_f2[(size_t)n * OUT_C] + lane);
    acc.x *= dn; acc.y *= dn; acc.z *= dn; acc.w *= dn;

    int i = start;
    for (; i + 4 <= end; i += 4) {
        int s0 = g_src[i], s1 = g_src[i + 1], s2 = g_src[i + 2], s3 = g_src[i + 3];
        float d0 = g_dinv[s0], d1 = g_dinv[s1], d2 = g_dinv[s2], d3 = g_dinv[s3];
        float4 v0 = __ldg((const float4*)&g_f2[(size_t)s0 * OUT_C] + lane);
        float4 v1 = __ldg((const float4*)&g_f2[(size_t)s1 * OUT_C] + lane);
        float4 v2 = __ldg((const float4*)&g_f2[(size_t)s2 * OUT_C] + lane);
        float4 v3 = __ldg((const float4*)&g_f2[(size_t)s3 * OUT_C] + lane);
        acc.x += v0.x * d0 + v1.x * d1 + v2.x * d2 + v3.x * d3;
        acc.y += v0.y * d0 + v1.y * d1 + v2.y * d2 + v3.y * d3;
        acc.z += v0.z * d0 + v1.z * d1 + v2.z * d2 + v3.z * d3;
        acc.w += v0.w * d0 + v1.w * d1 + v2.w * d2 + v3.w * d3;
    }
    for (; i < end; ++i) {
        int s = g_src[i];
        float ds = g_dinv[s];
        float4 v = __ldg((const float4*)&g_f2[(size_t)s * OUT_C] + lane);
        acc.x += v.x * ds; acc.y += v.y * ds; acc.z += v.z * ds; acc.w += v.w * ds;
    }
    float4 bb = __ldg((const float4*)b2 + lane);
    acc.x = acc.x * dn + bb.x; acc.y = acc.y * dn + bb.y;
    acc.z = acc.z * dn + bb.z; acc.w = acc.w * dn + bb.w;
    *((float4*)&out[(size_t)n * OUT_C] + lane) = acc;
}

// ---------------- launch ----------------------------------------------------
extern "C" void kernel_launch(void* const* d_in, const int* in_sizes, int n_in,
                              void* d_out, int out_size) {
    const float* features = (const float*)d_in[0];
    const void*  edge_idx = d_in[1];
    const float* W1 = (const float*)d_in[2];
    const float* b1 = (const float*)d_in[3];
    const float* W2 = (const float*)d_in[4];
    const float* b2 = (const float*)d_in[5];
    float* out = (float*)d_out;

    int M = in_sizes[0] / IN_C;       // 50000
    int E = in_sizes[1] / 2;          // 800000

    prep_kernel<<<(M + 255) / 256, 256>>>((const long long*)edge_idx, E, M);
    count_deg_kernel<<<(E + 255) / 256, 256>>>(edge_idx, E);
    scan1_kernel<<<SCAN_B, 256>>>(M);
    scan2_kernel<<<1, 256>>>();
    scan3_kernel<<<SCAN_B, 256>>>(M, E);
    fill_kernel<<<(E + 255) / 256, 256>>>(edge_idx, E);

    int gblocks = (M + 127) / 128;    // 391
    gemm1_kernel<<<gblocks, 256>>>(features, W1, M);

    long long t1 = (long long)M * 32;
    gather1_kernel<<<(unsigned)((t1 + 255) / 256), 256>>>(M);

    gemm2_kernel<<<gblocks, 256>>>(W2, b1, M);

    long long t2 = (long long)M * 16;
    gather2_kernel<<<(unsigned)((t2 + 255) / 256), 256>>>(out, b2, M);
}

// round 7
// speedup vs baseline: 1.0971x; 1.0971x over previous
#include <cuda_runtime.h>
#include <mma.h>
#include <cstdint>

using namespace nvcuda;

#define NODES_MAX 50000
#define PAD_M     50176      // 392*128, pad for unguarded wmma stores
#define E_MAX     1000000
#define IN_C  256
#define HID_C 128
#define OUT_C 64

#define SCAN_B    196        // scan blocks: 196*256 = 50176 >= NODES_MAX

// ---------------- scratch ----------------------------------------------------
__device__ float g_f1[PAD_M * HID_C];        // gemm1 raw output (X@W1)
__device__ float g_a1[NODES_MAX * HID_C];    // relu(agg1 + b1)  (gemm2 input)
__device__ float g_f2[PAD_M * OUT_C];        // gemm2 raw output
__device__ float g_dinv[NODES_MAX];
__device__ int   g_deg [NODES_MAX];
__device__ int   g_row_start[NODES_MAX + 1];
__device__ int   g_cursor[NODES_MAX];
__device__ int   g_src[E_MAX];               // CSR-by-dst: source node per slot
__device__ int   g_bsum[SCAN_B];
__device__ int   g_boff[SCAN_B];
__device__ int   g_is64;

// ---------------- cp.async helpers ------------------------------------------
__device__ __forceinline__ void cp16(void* smem, const void* gsrc, int szbytes) {
    uint32_t sa = (uint32_t)__cvta_generic_to_shared(smem);
    asm volatile("cp.async.cg.shared.global [%0], [%1], 16, %2;"
                 :: "r"(sa), "l"(gsrc), "r"(szbytes));
}
#define CP_COMMIT()  asm volatile("cp.async.commit_group;" ::: "memory")
#define CP_WAIT1()   asm volatile("cp.async.wait_group 1;" ::: "memory")
#define CP_WAIT0()   asm volatile("cp.async.wait_group 0;" ::: "memory")

// ---------------- prep: zero deg + dtype detect ------------------------------
__global__ void prep_kernel(const long long* __restrict__ p, int E, int M) {
    int i = blockIdx.x * blockDim.x + threadIdx.x;
    if (i < M) g_deg[i] = 0;
    if (blockIdx.x == 0) {
        __shared__ int bad;
        if (threadIdx.x == 0) bad = 0;
        __syncthreads();
        if ((int)threadIdx.x < 256 && (int)threadIdx.x < E) {
            long long v = p[threadIdx.x];
            if (v < 0 || v >= (long long)M) bad = 1;
        }
        __syncthreads();
        if (threadIdx.x == 0) g_is64 = bad ? 0 : 1;
    }
}

__device__ __forceinline__ void get_edge(const void* ei, int e, int E, int is64,
                                         int& s, int& d) {
    if (is64) {
        const long long* p = (const long long*)ei;
        s = (int)p[e]; d = (int)p[E + e];
    } else {
        const int* p = (const int*)ei;
        s = p[e]; d = p[E + e];
    }
}

__global__ void count_deg_kernel(const void* __restrict__ ei, int E) {
    int e = blockIdx.x * blockDim.x + threadIdx.x;
    if (e >= E) return;
    int s, d;
    get_edge(ei, e, E, g_is64, s, d);
    atomicAdd(&g_deg[d], 1);
}

// ---------------- hierarchical scan -----------------------------------------
__global__ __launch_bounds__(256) void scan1_kernel(int M) {
    __shared__ int red[8];
    int i = blockIdx.x * 256 + threadIdx.x;
    int d = (i < M) ? g_deg[i] : 0;
    if (i < M) g_dinv[i] = rsqrtf((float)(d + 1));
    int v = d;
    #pragma unroll
    for (int off = 16; off > 0; off >>= 1) v += __shfl_down_sync(0xffffffffu, v, off);
    if ((threadIdx.x & 31) == 0) red[threadIdx.x >> 5] = v;
    __syncthreads();
    if (threadIdx.x < 8) {
        int s = red[threadIdx.x];
        #pragma unroll
        for (int off = 4; off > 0; off >>= 1) s += __shfl_down_sync(0xffu, s, off);
        if (threadIdx.x == 0) g_bsum[blockIdx.x] = s;
    }
}

__global__ __launch_bounds__(256) void scan2_kernel() {
    __shared__ int sm[256];
    int t = threadIdx.x;
    sm[t] = (t < SCAN_B) ? g_bsum[t] : 0;
    __syncthreads();
    #pragma unroll
    for (int off = 1; off < 256; off <<= 1) {
        int v = (t >= off) ? sm[t - off] : 0;
        __syncthreads();
        sm[t] += v;
        __syncthreads();
    }
    if (t < SCAN_B) g_boff[t] = (t > 0) ? sm[t - 1] : 0;
}

__global__ __launch_bounds__(256) void scan3_kernel(int M, int E) {
    __shared__ int sm[256];
    int t = threadIdx.x;
    int i = blockIdx.x * 256 + t;
    int d = (i < M) ? g_deg[i] : 0;
    sm[t] = d;
    __syncthreads();
    #pragma unroll
    for (int off = 1; off < 256; off <<= 1) {
        int v = (t >= off) ? sm[t - off] : 0;
        __syncthreads();
        sm[t] += v;
        __syncthreads();
    }
    if (i < M) {
        int rs = g_boff[blockIdx.x] + sm[t] - d;
        g_row_start[i] = rs;
        g_cursor[i]    = rs;
    }
    if (i == M - 1) g_row_start[M] = E;
}

__global__ void fill_kernel(const void* __restrict__ ei, int E) {
    int e = blockIdx.x * blockDim.x + threadIdx.x;
    if (e >= E) return;
    int s, d;
    get_edge(ei, e, E, g_is64, s, d);
    int pos = atomicAdd(&g_cursor[d], 1);
    g_src[pos] = s;
}

// ---------------- GEMM1 (TF32, cp.async double-buffered): g_f1 = X @ W1 -----
// BM=128 BN=128 BK=16, 8 warps, warp tile 32x64 (2x4 frags), 16 k-tiles.
#define NT1 (IN_C / 16)
__global__ __launch_bounds__(256, 2) void gemm1_kernel(
    const float* __restrict__ A, const float* __restrict__ W, int M) {
    __shared__ float As[2][128][20];
    __shared__ float Bs[2][16][136];
    int tid = threadIdx.x;
    int wid = tid >> 5;
    int wm = wid & 3;
    int wn = wid >> 2;
    int bm = blockIdx.x * 128;

    wmma::fragment<wmma::accumulator, 16, 16, 8, float> c[2][4];
    #pragma unroll
    for (int i = 0; i < 2; i++)
        #pragma unroll
        for (int j = 0; j < 4; j++) wmma::fill_fragment(c[i][j], 0.f);

    auto issue = [&](int kt, int buf) {
        int k0 = kt * 16;
        #pragma unroll
        for (int i = 0; i < 2; ++i) {
            int idx = tid * 2 + i;
            int r = idx >> 2, c4 = (idx & 3) * 4;
            int gm = bm + r;
            int gmc = (gm < M) ? gm : (M - 1);
            cp16(&As[buf][r][c4], &A[(size_t)gmc * IN_C + k0 + c4],
                 (gm < M) ? 16 : 0);
        }
        #pragma unroll
        for (int i = 0; i < 2; ++i) {
            int idx = tid * 2 + i;
            int kk = idx >> 5, n4 = (idx & 31) * 4;
            cp16(&Bs[buf][kk][n4], &W[(size_t)(k0 + kk) * HID_C + n4], 16);
        }
        CP_COMMIT();
    };

    auto compute = [&](int buf) {
        #pragma unroll
        for (int ks = 0; ks < 16; ks += 8) {
            wmma::fragment<wmma::matrix_a, 16, 16, 8, wmma::precision::tf32, wmma::row_major> a[2];
            wmma::fragment<wmma::matrix_b, 16, 16, 8, wmma::precision::tf32, wmma::row_major> b[4];
            #pragma unroll
            for (int i = 0; i < 2; i++) {
                wmma::load_matrix_sync(a[i], &As[buf][wm * 32 + i * 16][ks], 20);
                #pragma unroll
                for (int t = 0; t < a[i].num_elements; t++)
                    a[i].x[t] = wmma::__float_to_tf32(a[i].x[t]);
            }
            #pragma unroll
            for (int j = 0; j < 4; j++) {
                wmma::load_matrix_sync(b[j], &Bs[buf][ks][wn * 64 + j * 16], 136);
                #pragma unroll
                for (int t = 0; t < b[j].num_elements; t++)
                    b[j].x[t] = wmma::__float_to_tf32(b[j].x[t]);
            }
            #pragma unroll
            for (int i = 0; i < 2; i++)
                #pragma unroll
                for (int j = 0; j < 4; j++)
                    wmma::mma_sync(c[i][j], a[i], b[j], c[i][j]);
        }
    };

    issue(0, 0);
    for (int t = 0; t < NT1; ++t) {
        if (t + 1 < NT1) {
            issue(t + 1, (t + 1) & 1);
            CP_WAIT1();
        } else {
            CP_WAIT0();
        }
        __syncthreads();
        compute(t & 1);
        __syncthreads();
    }

    #pragma unroll
    for (int i = 0; i < 2; i++)
        #pragma unroll
        for (int j = 0; j < 4; j++) {
            size_t off = (size_t)(bm + wm * 32 + i * 16) * HID_C + wn * 64 + j * 16;
            wmma::store_matrix_sync(&g_f1[off], c[i][j], HID_C, wmma::mem_row_major);
        }
}

// ---------------- gather layer 1 (warp per node), fused +b1, relu -----------
__global__ __launch_bounds__(256) void gather1_kernel(const float* __restrict__ b1, int M) {
    int w    = (blockIdx.x * blockDim.x + threadIdx.x) >> 5;
    int lane = threadIdx.x & 31;
    if (w >= M) return;
    int start = g_row_start[w];
    int end   = g_row_start[w + 1];
    float dn = g_dinv[w];
    float4 acc = __ldg((const float4*)&g_f1[(size_t)w * HID_C] + lane);
    acc.x *= dn; acc.y *= dn; acc.z *= dn; acc.w *= dn;

    int i = start;
    for (; i + 4 <= end; i += 4) {
        int s0 = g_src[i], s1 = g_src[i + 1], s2 = g_src[i + 2], s3 = g_src[i + 3];
        float d0 = g_dinv[s0], d1 = g_dinv[s1], d2 = g_dinv[s2], d3 = g_dinv[s3];
        float4 v0 = __ldg((const float4*)&g_f1[(size_t)s0 * HID_C] + lane);
        float4 v1 = __ldg((const float4*)&g_f1[(size_t)s1 * HID_C] + lane);
        float4 v2 = __ldg((const float4*)&g_f1[(size_t)s2 * HID_C] + lane);
        float4 v3 = __ldg((const float4*)&g_f1[(size_t)s3 * HID_C] + lane);
        acc.x += v0.x * d0 + v1.x * d1 + v2.x * d2 + v3.x * d3;
        acc.y += v0.y * d0 + v1.y * d1 + v2.y * d2 + v3.y * d3;
        acc.z += v0.z * d0 + v1.z * d1 + v2.z * d2 + v3.z * d3;
        acc.w += v0.w * d0 + v1.w * d1 + v2.w * d2 + v3.w * d3;
    }
    for (; i < end; ++i) {
        int s = g_src[i];
        float ds = g_dinv[s];
        float4 v = __ldg((const float4*)&g_f1[(size_t)s * HID_C] + lane);
        acc.x += v.x * ds; acc.y += v.y * ds; acc.z += v.z * ds; acc.w += v.w * ds;
    }
    float4 bb = __ldg((const float4*)b1 + lane);
    acc.x = fmaxf(fmaf(acc.x, dn, bb.x), 0.f);
    acc.y = fmaxf(fmaf(acc.y, dn, bb.y), 0.f);
    acc.z = fmaxf(fmaf(acc.z, dn, bb.z), 0.f);
    acc.w = fmaxf(fmaf(acc.w, dn, bb.w), 0.f);
    *((float4*)&g_a1[(size_t)w * HID_C] + lane) = acc;
}

// ---------------- GEMM2 (TF32, cp.async double-buffered): g_f2 = a1 @ W2 ----
// BM=128 BN=64 BK=16, 8 warps, warp tile 32x32 (2x2 frags), 8 k-tiles.
#define NT2 (HID_C / 16)
__global__ __launch_bounds__(256, 2) void gemm2_kernel(
    const float* __restrict__ W, int M) {
    __shared__ float As[2][128][20];
    __shared__ float Bs[2][16][72];
    int tid = threadIdx.x;
    int wid = tid >> 5;
    int wm = wid & 3;
    int wn = wid >> 2;
    int bm = blockIdx.x * 128;

    wmma::fragment<wmma::accumulator, 16, 16, 8, float> c[2][2];
    #pragma unroll
    for (int i = 0; i < 2; i++)
        #pragma unroll
        for (int j = 0; j < 2; j++) wmma::fill_fragment(c[i][j], 0.f);

    auto issue = [&](int kt, int buf) {
        int k0 = kt * 16;
        #pragma unroll
        for (int i = 0; i < 2; ++i) {
            int idx = tid * 2 + i;
            int r = idx >> 2, c4 = (idx & 3) * 4;
            int gm = bm + r;
            int gmc = (gm < M) ? gm : (M - 1);
            cp16(&As[buf][r][c4], &g_a1[(size_t)gmc * HID_C + k0 + c4],
                 (gm < M) ? 16 : 0);
        }
        {
            int kk = tid >> 4, n4 = (tid & 15) * 4;
            cp16(&Bs[buf][kk][n4], &W[(size_t)(k0 + kk) * OUT_C + n4], 16);
        }
        CP_COMMIT();
    };

    auto compute = [&](int buf) {
        #pragma unroll
        for (int ks = 0; ks < 16; ks += 8) {
            wmma::fragment<wmma::matrix_a, 16, 16, 8, wmma::precision::tf32, wmma::row_major> a[2];
            wmma::fragment<wmma::matrix_b, 16, 16, 8, wmma::precision::tf32, wmma::row_major> b[2];
            #pragma unroll
            for (int i = 0; i < 2; i++) {
                wmma::load_matrix_sync(a[i], &As[buf][wm * 32 + i * 16][ks], 20);
                #pragma unroll
                for (int t = 0; t < a[i].num_elements; t++)
                    a[i].x[t] = wmma::__float_to_tf32(a[i].x[t]);
            }
            #pragma unroll
            for (int j = 0; j < 2; j++) {
                wmma::load_matrix_sync(b[j], &Bs[buf][ks][wn * 32 + j * 16], 72);
                #pragma unroll
                for (int t = 0; t < b[j].num_elements; t++)
                    b[j].x[t] = wmma::__float_to_tf32(b[j].x[t]);
            }
            #pragma unroll
            for (int i = 0; i < 2; i++)
                #pragma unroll
                for (int j = 0; j < 2; j++)
                    wmma::mma_sync(c[i][j], a[i], b[j], c[i][j]);
        }
    };

    issue(0, 0);
    for (int t = 0; t < NT2; ++t) {
        if (t + 1 < NT2) {
            issue(t + 1, (t + 1) & 1);
            CP_WAIT1();
        } else {
            CP_WAIT0();
        }
        __syncthreads();
        compute(t & 1);
        __syncthreads();
    }

    #pragma unroll
    for (int i = 0; i < 2; i++)
        #pragma unroll
        for (int j = 0; j < 2; j++) {
            size_t off = (size_t)(bm + wm * 32 + i * 16) * OUT_C + wn * 32 + j * 16;
            wmma::store_matrix_sync(&g_f2[off], c[i][j], OUT_C, wmma::mem_row_major);
        }
}

// ---------------- gather layer 2 + bias (16 lanes per node) -----------------
__global__ __launch_bounds__(256) void gather2_kernel(
    float* __restrict__ out, const float* __restrict__ b2, int M) {
    int t    = blockIdx.x * blockDim.x + threadIdx.x;
    int n    = t >> 4;
    int lane = t & 15;
    if (n >= M) return;
    int start = g_row_start[n];
    int end   = g_row_start[n + 1];
    float dn = g_dinv[n];
    float4 acc = __ldg((const float4*)&g_f2[(size_t)n * OUT_C] + lane);
    acc.x *= dn; acc.y *= dn; acc.z *= dn; acc.w *= dn;

    int i = start;
    for (; i + 4 <= end; i += 4) {
        int s0 = g_src[i], s1 = g_src[i + 1], s2 = g_src[i + 2], s3 = g_src[i + 3];
        float d0 = g_dinv[s0], d1 = g_dinv[s1], d2 = g_dinv[s2], d3 = g_dinv[s3];
        float4 v0 = __ldg((const float4*)&g_f2[(size_t)s0 * OUT_C] + lane);
        float4 v1 = __ldg((const float4*)&g_f2[(size_t)s1 * OUT_C] + lane);
        float4 v2 = __ldg((const float4*)&g_f2[(size_t)s2 * OUT_C] + lane);
        float4 v3 = __ldg((const float4*)&g_f2[(size_t)s3 * OUT_C] + lane);
        acc.x += v0.x * d0 + v1.x * d1 + v2.x * d2 + v3.x * d3;
        acc.y += v0.y * d0 + v1.y * d1 + v2.y * d2 + v3.y * d3;
        acc.z += v0.z * d0 + v1.z * d1 + v2.z * d2 + v3.z * d3;
        acc.w += v0.w * d0 + v1.w * d1 + v2.w * d2 + v3.w * d3;
    }
    for (; i < end; ++i) {
        int s = g_src[i];
        float ds = g_dinv[s];
        float4 v = __ldg((const float4*)&g_f2[(size_t)s * OUT_C] + lane);
        acc.x += v.x * ds; acc.y += v.y * ds; acc.z += v.z * ds; acc.w += v.w * ds;
    }
    float4 bb = __ldg((const float4*)b2 + lane);
    acc.x = acc.x * dn + bb.x; acc.y = acc.y * dn + bb.y;
    acc.z = acc.z * dn + bb.z; acc.w = acc.w * dn + bb.w;
    *((float4*)&out[(size_t)n * OUT_C] + lane) = acc;
}

// ---------------- launch ----------------------------------------------------
extern "C" void kernel_launch(void* const* d_in, const int* in_sizes, int n_in,
                              void* d_out, int out_size) {
    const float* features = (const float*)d_in[0];
    const void*  edge_idx = d_in[1];
    const float* W1 = (const float*)d_in[2];
    const float* b1 = (const float*)d_in[3];
    const float* W2 = (const float*)d_in[4];
    const float* b2 = (const float*)d_in[5];
    float* out = (float*)d_out;

    int M = in_sizes[0] / IN_C;       // 50000
    int E = in_sizes[1] / 2;          // 800000

    prep_kernel<<<(M + 255) / 256, 256>>>((const long long*)edge_idx, E, M);
    count_deg_kernel<<<(E + 255) / 256, 256>>>(edge_idx, E);
    scan1_kernel<<<SCAN_B, 256>>>(M);
    scan2_kernel<<<1, 256>>>();
    scan3_kernel<<<SCAN_B, 256>>>(M, E);
    fill_kernel<<<(E + 255) / 256, 256>>>(edge_idx, E);

    int gblocks = (M + 127) / 128;    // 391
    gemm1_kernel<<<gblocks, 256>>>(features, W1, M);

    long long t1 = (long long)M * 32;
    gather1_kernel<<<(unsigned)((t1 + 255) / 256), 256>>>(b1, M);

    gemm2_kernel<<<gblocks, 256>>>(W2, M);

    long long t2 = (long long)M * 16;
    gather2_kernel<<<(unsigned)((t2 + 255) / 256), 256>>>(out, b2, M);
}

// round 8
// speedup vs baseline: 1.2677x; 1.1555x over previous
#include <cuda_runtime.h>
#include <mma.h>
#include <cstdint>

using namespace nvcuda;

#define NODES_MAX 50000
#define PAD_M     50176      // 392*128, pad for unguarded wmma stores
#define E_MAX     1000000
#define IN_C  256
#define HID_C 128
#define OUT_C 64

#define SCAN_B    196        // scan blocks: 196*256 = 50176 >= NODES_MAX

// ---------------- scratch ----------------------------------------------------
__device__ float g_f1[PAD_M * HID_C];        // gemm1 raw output (X@W1)
__device__ float g_a1[NODES_MAX * HID_C];    // relu(agg1 + b1)  (gemm2 input)
__device__ float g_f2[PAD_M * OUT_C];        // gemm2 raw output
__device__ float g_dinv[NODES_MAX];
__device__ int   g_deg [NODES_MAX];
__device__ int   g_row_start[NODES_MAX + 1];
__device__ int   g_cursor[NODES_MAX];
__device__ int   g_src[E_MAX];               // CSR-by-dst: source node per slot
__device__ int   g_bsum[SCAN_B];
__device__ int   g_boff[SCAN_B];
__device__ int   g_is64;

// ---------------- side stream for graph-fork (created at static init) -------
namespace {
struct SideStream {
    cudaStream_t s2 = nullptr;
    cudaEvent_t  ev_fork = nullptr, ev_join = nullptr;
    SideStream() {
        cudaStreamCreateWithFlags(&s2, cudaStreamNonBlocking);
        cudaEventCreateWithFlags(&ev_fork, cudaEventDisableTiming);
        cudaEventCreateWithFlags(&ev_join, cudaEventDisableTiming);
    }
};
SideStream g_ss;
}

// ---------------- cp.async helpers ------------------------------------------
__device__ __forceinline__ void cp16(void* smem, const void* gsrc, int szbytes) {
    uint32_t sa = (uint32_t)__cvta_generic_to_shared(smem);
    asm volatile("cp.async.cg.shared.global [%0], [%1], 16, %2;"
                 :: "r"(sa), "l"(gsrc), "r"(szbytes));
}
#define CP_COMMIT()  asm volatile("cp.async.commit_group;" ::: "memory")
#define CP_WAIT1()   asm volatile("cp.async.wait_group 1;" ::: "memory")
#define CP_WAIT0()   asm volatile("cp.async.wait_group 0;" ::: "memory")

// ---------------- prep: zero deg + dtype detect ------------------------------
__global__ void prep_kernel(const long long* __restrict__ p, int E, int M) {
    int i = blockIdx.x * blockDim.x + threadIdx.x;
    if (i < M) g_deg[i] = 0;
    if (blockIdx.x == 0) {
        __shared__ int bad;
        if (threadIdx.x == 0) bad = 0;
        __syncthreads();
        if ((int)threadIdx.x < 256 && (int)threadIdx.x < E) {
            long long v = p[threadIdx.x];
            if (v < 0 || v >= (long long)M) bad = 1;
        }
        __syncthreads();
        if (threadIdx.x == 0) g_is64 = bad ? 0 : 1;
    }
}

__device__ __forceinline__ void get_edge(const void* ei, int e, int E, int is64,
                                         int& s, int& d) {
    if (is64) {
        const long long* p = (const long long*)ei;
        s = (int)p[e]; d = (int)p[E + e];
    } else {
        const int* p = (const int*)ei;
        s = p[e]; d = p[E + e];
    }
}

__global__ void count_deg_kernel(const void* __restrict__ ei, int E) {
    int e = blockIdx.x * blockDim.x + threadIdx.x;
    if (e >= E) return;
    int s, d;
    get_edge(ei, e, E, g_is64, s, d);
    atomicAdd(&g_deg[d], 1);
}

// ---------------- hierarchical scan -----------------------------------------
__global__ __launch_bounds__(256) void scan1_kernel(int M) {
    __shared__ int red[8];
    int i = blockIdx.x * 256 + threadIdx.x;
    int d = (i < M) ? g_deg[i] : 0;
    if (i < M) g_dinv[i] = rsqrtf((float)(d + 1));
    int v = d;
    #pragma unroll
    for (int off = 16; off > 0; off >>= 1) v += __shfl_down_sync(0xffffffffu, v, off);
    if ((threadIdx.x & 31) == 0) red[threadIdx.x >> 5] = v;
    __syncthreads();
    if (threadIdx.x < 8) {
        int s = red[threadIdx.x];
        #pragma unroll
        for (int off = 4; off > 0; off >>= 1) s += __shfl_down_sync(0xffu, s, off);
        if (threadIdx.x == 0) g_bsum[blockIdx.x] = s;
    }
}

__global__ __launch_bounds__(256) void scan2_kernel() {
    __shared__ int sm[256];
    int t = threadIdx.x;
    sm[t] = (t < SCAN_B) ? g_bsum[t] : 0;
    __syncthreads();
    #pragma unroll
    for (int off = 1; off < 256; off <<= 1) {
        int v = (t >= off) ? sm[t - off] : 0;
        __syncthreads();
        sm[t] += v;
        __syncthreads();
    }
    if (t < SCAN_B) g_boff[t] = (t > 0) ? sm[t - 1] : 0;
}

__global__ __launch_bounds__(256) void scan3_kernel(int M, int E) {
    __shared__ int sm[256];
    int t = threadIdx.x;
    int i = blockIdx.x * 256 + t;
    int d = (i < M) ? g_deg[i] : 0;
    sm[t] = d;
    __syncthreads();
    #pragma unroll
    for (int off = 1; off < 256; off <<= 1) {
        int v = (t >= off) ? sm[t - off] : 0;
        __syncthreads();
        sm[t] += v;
        __syncthreads();
    }
    if (i < M) {
        int rs = g_boff[blockIdx.x] + sm[t] - d;
        g_row_start[i] = rs;
        g_cursor[i]    = rs;
    }
    if (i == M - 1) g_row_start[M] = E;
}

__global__ void fill_kernel(const void* __restrict__ ei, int E) {
    int e = blockIdx.x * blockDim.x + threadIdx.x;
    if (e >= E) return;
    int s, d;
    get_edge(ei, e, E, g_is64, s, d);
    int pos = atomicAdd(&g_cursor[d], 1);
    g_src[pos] = s;
}

// ---------------- GEMM1 (TF32, cp.async double-buffered): g_f1 = X @ W1 -----
#define NT1 (IN_C / 16)
__global__ __launch_bounds__(256, 2) void gemm1_kernel(
    const float* __restrict__ A, const float* __restrict__ W, int M) {
    __shared__ float As[2][128][20];
    __shared__ float Bs[2][16][136];
    int tid = threadIdx.x;
    int wid = tid >> 5;
    int wm = wid & 3;
    int wn = wid >> 2;
    int bm = blockIdx.x * 128;

    wmma::fragment<wmma::accumulator, 16, 16, 8, float> c[2][4];
    #pragma unroll
    for (int i = 0; i < 2; i++)
        #pragma unroll
        for (int j = 0; j < 4; j++) wmma::fill_fragment(c[i][j], 0.f);

    auto issue = [&](int kt, int buf) {
        int k0 = kt * 16;
        #pragma unroll
        for (int i = 0; i < 2; ++i) {
            int idx = tid * 2 + i;
            int r = idx >> 2, c4 = (idx & 3) * 4;
            int gm = bm + r;
            int gmc = (gm < M) ? gm : (M - 1);
            cp16(&As[buf][r][c4], &A[(size_t)gmc * IN_C + k0 + c4],
                 (gm < M) ? 16 : 0);
        }
        #pragma unroll
        for (int i = 0; i < 2; ++i) {
            int idx = tid * 2 + i;
            int kk = idx >> 5, n4 = (idx & 31) * 4;
            cp16(&Bs[buf][kk][n4], &W[(size_t)(k0 + kk) * HID_C + n4], 16);
        }
        CP_COMMIT();
    };

    auto compute = [&](int buf) {
        #pragma unroll
        for (int ks = 0; ks < 16; ks += 8) {
            wmma::fragment<wmma::matrix_a, 16, 16, 8, wmma::precision::tf32, wmma::row_major> a[2];
            wmma::fragment<wmma::matrix_b, 16, 16, 8, wmma::precision::tf32, wmma::row_major> b[4];
            #pragma unroll
            for (int i = 0; i < 2; i++) {
                wmma::load_matrix_sync(a[i], &As[buf][wm * 32 + i * 16][ks], 20);
                #pragma unroll
                for (int t = 0; t < a[i].num_elements; t++)
                    a[i].x[t] = wmma::__float_to_tf32(a[i].x[t]);
            }
            #pragma unroll
            for (int j = 0; j < 4; j++) {
                wmma::load_matrix_sync(b[j], &Bs[buf][ks][wn * 64 + j * 16], 136);
                #pragma unroll
                for (int t = 0; t < b[j].num_elements; t++)
                    b[j].x[t] = wmma::__float_to_tf32(b[j].x[t]);
            }
            #pragma unroll
            for (int i = 0; i < 2; i++)
                #pragma unroll
                for (int j = 0; j < 4; j++)
                    wmma::mma_sync(c[i][j], a[i], b[j], c[i][j]);
        }
    };

    issue(0, 0);
    for (int t = 0; t < NT1; ++t) {
        if (t + 1 < NT1) {
            issue(t + 1, (t + 1) & 1);
            CP_WAIT1();
        } else {
            CP_WAIT0();
        }
        __syncthreads();
        compute(t & 1);
        __syncthreads();
    }

    #pragma unroll
    for (int i = 0; i < 2; i++)
        #pragma unroll
        for (int j = 0; j < 4; j++) {
            size_t off = (size_t)(bm + wm * 32 + i * 16) * HID_C + wn * 64 + j * 16;
            wmma::store_matrix_sync(&g_f1[off], c[i][j], HID_C, wmma::mem_row_major);
        }
}

// ---------------- gather layer 1 (warp per node), fused +b1, relu -----------
__global__ __launch_bounds__(256) void gather1_kernel(const float* __restrict__ b1, int M) {
    int w    = (blockIdx.x * blockDim.x + threadIdx.x) >> 5;
    int lane = threadIdx.x & 31;
    if (w >= M) return;
    int start = g_row_start[w];
    int end   = g_row_start[w + 1];
    float dn = g_dinv[w];
    float4 acc = __ldg((const float4*)&g_f1[(size_t)w * HID_C] + lane);
    acc.x *= dn; acc.y *= dn; acc.z *= dn; acc.w *= dn;

    int i = start;
    for (; i + 4 <= end; i += 4) {
        int s0 = g_src[i], s1 = g_src[i + 1], s2 = g_src[i + 2], s3 = g_src[i + 3];
        float d0 = g_dinv[s0], d1 = g_dinv[s1], d2 = g_dinv[s2], d3 = g_dinv[s3];
        float4 v0 = __ldg((const float4*)&g_f1[(size_t)s0 * HID_C] + lane);
        float4 v1 = __ldg((const float4*)&g_f1[(size_t)s1 * HID_C] + lane);
        float4 v2 = __ldg((const float4*)&g_f1[(size_t)s2 * HID_C] + lane);
        float4 v3 = __ldg((const float4*)&g_f1[(size_t)s3 * HID_C] + lane);
        acc.x += v0.x * d0 + v1.x * d1 + v2.x * d2 + v3.x * d3;
        acc.y += v0.y * d0 + v1.y * d1 + v2.y * d2 + v3.y * d3;
        acc.z += v0.z * d0 + v1.z * d1 + v2.z * d2 + v3.z * d3;
        acc.w += v0.w * d0 + v1.w * d1 + v2.w * d2 + v3.w * d3;
    }
    for (; i < end; ++i) {
        int s = g_src[i];
        float ds = g_dinv[s];
        float4 v = __ldg((const float4*)&g_f1[(size_t)s * HID_C] + lane);
        acc.x += v.x * ds; acc.y += v.y * ds; acc.z += v.z * ds; acc.w += v.w * ds;
    }
    float4 bb = __ldg((const float4*)b1 + lane);
    acc.x = fmaxf(fmaf(acc.x, dn, bb.x), 0.f);
    acc.y = fmaxf(fmaf(acc.y, dn, bb.y), 0.f);
    acc.z = fmaxf(fmaf(acc.z, dn, bb.z), 0.f);
    acc.w = fmaxf(fmaf(acc.w, dn, bb.w), 0.f);
    *((float4*)&g_a1[(size_t)w * HID_C] + lane) = acc;
}

// ---------------- GEMM2 (TF32, cp.async double-buffered): g_f2 = a1 @ W2 ----
#define NT2 (HID_C / 16)
__global__ __launch_bounds__(256, 2) void gemm2_kernel(
    const float* __restrict__ W, int M) {
    __shared__ float As[2][128][20];
    __shared__ float Bs[2][16][72];
    int tid = threadIdx.x;
    int wid = tid >> 5;
    int wm = wid & 3;
    int wn = wid >> 2;
    int bm = blockIdx.x * 128;

    wmma::fragment<wmma::accumulator, 16, 16, 8, float> c[2][2];
    #pragma unroll
    for (int i = 0; i < 2; i++)
        #pragma unroll
        for (int j = 0; j < 2; j++) wmma::fill_fragment(c[i][j], 0.f);

    auto issue = [&](int kt, int buf) {
        int k0 = kt * 16;
        #pragma unroll
        for (int i = 0; i < 2; ++i) {
            int idx = tid * 2 + i;
            int r = idx >> 2, c4 = (idx & 3) * 4;
            int gm = bm + r;
            int gmc = (gm < M) ? gm : (M - 1);
            cp16(&As[buf][r][c4], &g_a1[(size_t)gmc * HID_C + k0 + c4],
                 (gm < M) ? 16 : 0);
        }
        {
            int kk = tid >> 4, n4 = (tid & 15) * 4;
            cp16(&Bs[buf][kk][n4], &W[(size_t)(k0 + kk) * OUT_C + n4], 16);
        }
        CP_COMMIT();
    };

    auto compute = [&](int buf) {
        #pragma unroll
        for (int ks = 0; ks < 16; ks += 8) {
            wmma::fragment<wmma::matrix_a, 16, 16, 8, wmma::precision::tf32, wmma::row_major> a[2];
            wmma::fragment<wmma::matrix_b, 16, 16, 8, wmma::precision::tf32, wmma::row_major> b[2];
            #pragma unroll
            for (int i = 0; i < 2; i++) {
                wmma::load_matrix_sync(a[i], &As[buf][wm * 32 + i * 16][ks], 20);
                #pragma unroll
                for (int t = 0; t < a[i].num_elements; t++)
                    a[i].x[t] = wmma::__float_to_tf32(a[i].x[t]);
            }
            #pragma unroll
            for (int j = 0; j < 2; j++) {
                wmma::load_matrix_sync(b[j], &Bs[buf][ks][wn * 32 + j * 16], 72);
                #pragma unroll
                for (int t = 0; t < b[j].num_elements; t++)
                    b[j].x[t] = wmma::__float_to_tf32(b[j].x[t]);
            }
            #pragma unroll
            for (int i = 0; i < 2; i++)
                #pragma unroll
                for (int j = 0; j < 2; j++)
                    wmma::mma_sync(c[i][j], a[i], b[j], c[i][j]);
        }
    };

    issue(0, 0);
    for (int t = 0; t < NT2; ++t) {
        if (t + 1 < NT2) {
            issue(t + 1, (t + 1) & 1);
            CP_WAIT1();
        } else {
            CP_WAIT0();
        }
        __syncthreads();
        compute(t & 1);
        __syncthreads();
    }

    #pragma unroll
    for (int i = 0; i < 2; i++)
        #pragma unroll
        for (int j = 0; j < 2; j++) {
            size_t off = (size_t)(bm + wm * 32 + i * 16) * OUT_C + wn * 32 + j * 16;
            wmma::store_matrix_sync(&g_f2[off], c[i][j], OUT_C, wmma::mem_row_major);
        }
}

// ---------------- gather layer 2 + bias (16 lanes per node) -----------------
__global__ __launch_bounds__(256) void gather2_kernel(
    float* __restrict__ out, const float* __restrict__ b2, int M) {
    int t    = blockIdx.x * blockDim.x + threadIdx.x;
    int n    = t >> 4;
    int lane = t & 15;
    if (n >= M) return;
    int start = g_row_start[n];
    int end   = g_row_start[n + 1];
    float dn = g_dinv[n];
    float4 acc = __ldg((const float4*)&g_f2[(size_t)n * OUT_C] + lane);
    acc.x *= dn; acc.y *= dn; acc.z *= dn; acc.w *= dn;

    int i = start;
    for (; i + 4 <= end; i += 4) {
        int s0 = g_src[i], s1 = g_src[i + 1], s2 = g_src[i + 2], s3 = g_src[i + 3];
        float d0 = g_dinv[s0], d1 = g_dinv[s1], d2 = g_dinv[s2], d3 = g_dinv[s3];
        float4 v0 = __ldg((const float4*)&g_f2[(size_t)s0 * OUT_C] + lane);
        float4 v1 = __ldg((const float4*)&g_f2[(size_t)s1 * OUT_C] + lane);
        float4 v2 = __ldg((const float4*)&g_f2[(size_t)s2 * OUT_C] + lane);
        float4 v3 = __ldg((const float4*)&g_f2[(size_t)s3 * OUT_C] + lane);
        acc.x += v0.x * d0 + v1.x * d1 + v2.x * d2 + v3.x * d3;
        acc.y += v0.y * d0 + v1.y * d1 + v2.y * d2 + v3.y * d3;
        acc.z += v0.z * d0 + v1.z * d1 + v2.z * d2 + v3.z * d3;
        acc.w += v0.w * d0 + v1.w * d1 + v2.w * d2 + v3.w * d3;
    }
    for (; i < end; ++i) {
        int s = g_src[i];
        float ds = g_dinv[s];
        float4 v = __ldg((const float4*)&g_f2[(size_t)s * OUT_C] + lane);
        acc.x += v.x * ds; acc.y += v.y * ds; acc.z += v.z * ds; acc.w += v.w * ds;
    }
    float4 bb = __ldg((const float4*)b2 + lane);
    acc.x = acc.x * dn + bb.x; acc.y = acc.y * dn + bb.y;
    acc.z = acc.z * dn + bb.z; acc.w = acc.w * dn + bb.w;
    *((float4*)&out[(size_t)n * OUT_C] + lane) = acc;
}

// ---------------- launch ----------------------------------------------------
extern "C" void kernel_launch(void* const* d_in, const int* in_sizes, int n_in,
                              void* d_out, int out_size) {
    const float* features = (const float*)d_in[0];
    const void*  edge_idx = d_in[1];
    const float* W1 = (const float*)d_in[2];
    const float* b1 = (const float*)d_in[3];
    const float* W2 = (const float*)d_in[4];
    const float* b2 = (const float*)d_in[5];
    float* out = (float*)d_out;

    int M = in_sizes[0] / IN_C;       // 50000
    int E = in_sizes[1] / 2;          // 800000

    int gblocks = (M + 127) / 128;    // 391

    // Fork: gemm1 (independent of graph preprocessing) on side stream.
    cudaEventRecord(g_ss.ev_fork, 0);
    cudaStreamWaitEvent(g_ss.s2, g_ss.ev_fork, 0);
    gemm1_kernel<<<gblocks, 256, 0, g_ss.s2>>>(features, W1, M);
    cudaEventRecord(g_ss.ev_join, g_ss.s2);

    // Preprocessing chain on the main (capture) stream, concurrent with gemm1.
    prep_kernel<<<(M + 255) / 256, 256>>>((const long long*)edge_idx, E, M);
    count_deg_kernel<<<(E + 255) / 256, 256>>>(edge_idx, E);
    scan1_kernel<<<SCAN_B, 256>>>(M);
    scan2_kernel<<<1, 256>>>();
    scan3_kernel<<<SCAN_B, 256>>>(M, E);
    fill_kernel<<<(E + 255) / 256, 256>>>(edge_idx, E);

    // Join: gather1 needs both gemm1 output and the CSR.
    cudaStreamWaitEvent(0, g_ss.ev_join, 0);

    long long t1 = (long long)M * 32;
    gather1_kernel<<<(unsigned)((t1 + 255) / 256), 256>>>(b1, M);

    gemm2_kernel<<<gblocks, 256>>>(W2, M);

    long long t2 = (long long)M * 16;
    gather2_kernel<<<(unsigned)((t2 + 255) / 256), 256>>>(out, b2, M);
}

// round 9
// speedup vs baseline: 1.2744x; 1.0052x over previous
#include <cuda_runtime.h>
#include <cuda_fp16.h>
#include <mma.h>
#include <cstdint>

using namespace nvcuda;

#define NODES_MAX 50000
#define PAD_M     50176      // 392*128, pad for unguarded wmma stores
#define E_MAX     1000000
#define IN_C  256
#define HID_C 128
#define OUT_C 64

#define SCAN_B    196        // scan blocks: 196*256 = 50176 >= NODES_MAX

// ---------------- scratch ----------------------------------------------------
__device__ __half g_f1h[PAD_M * HID_C];      // gemm1 output (X@W1), fp16 messages
__device__ float  g_a1 [NODES_MAX * HID_C];  // relu(agg1 + b1)  (gemm2 input, fp32)
__device__ __half g_f2h[PAD_M * OUT_C];      // gemm2 output, fp16 messages
__device__ float  g_dinv[NODES_MAX];
__device__ int    g_deg [NODES_MAX];
__device__ int    g_row_start[NODES_MAX + 1];
__device__ int    g_cursor[NODES_MAX];
__device__ int    g_src[E_MAX];              // CSR-by-dst: source node per slot
__device__ int    g_bsum[SCAN_B];
__device__ int    g_boff[SCAN_B];
__device__ int    g_is64;

// ---------------- side stream for graph-fork (created at static init) -------
namespace {
struct SideStream {
    cudaStream_t s2 = nullptr;
    cudaEvent_t  ev_fork = nullptr, ev_join = nullptr;
    SideStream() {
        cudaStreamCreateWithFlags(&s2, cudaStreamNonBlocking);
        cudaEventCreateWithFlags(&ev_fork, cudaEventDisableTiming);
        cudaEventCreateWithFlags(&ev_join, cudaEventDisableTiming);
    }
};
SideStream g_ss;
}

// ---------------- cp.async helpers ------------------------------------------
__device__ __forceinline__ void cp16(void* smem, const void* gsrc, int szbytes) {
    uint32_t sa = (uint32_t)__cvta_generic_to_shared(smem);
    asm volatile("cp.async.cg.shared.global [%0], [%1], 16, %2;"
                 :: "r"(sa), "l"(gsrc), "r"(szbytes));
}
#define CP_COMMIT()  asm volatile("cp.async.commit_group;" ::: "memory")
#define CP_WAIT1()   asm volatile("cp.async.wait_group 1;" ::: "memory")
#define CP_WAIT0()   asm volatile("cp.async.wait_group 0;" ::: "memory")

// ---------------- prep: zero deg + dtype detect ------------------------------
__global__ void prep_kernel(const long long* __restrict__ p, int E, int M) {
    int i = blockIdx.x * blockDim.x + threadIdx.x;
    if (i < M) g_deg[i] = 0;
    if (blockIdx.x == 0) {
        __shared__ int bad;
        if (threadIdx.x == 0) bad = 0;
        __syncthreads();
        if ((int)threadIdx.x < 256 && (int)threadIdx.x < E) {
            long long v = p[threadIdx.x];
            if (v < 0 || v >= (long long)M) bad = 1;
        }
        __syncthreads();
        if (threadIdx.x == 0) g_is64 = bad ? 0 : 1;
    }
}

__device__ __forceinline__ void get_edge(const void* ei, int e, int E, int is64,
                                         int& s, int& d) {
    if (is64) {
        const long long* p = (const long long*)ei;
        s = (int)p[e]; d = (int)p[E + e];
    } else {
        const int* p = (const int*)ei;
        s = p[e]; d = p[E + e];
    }
}

__global__ void count_deg_kernel(const void* __restrict__ ei, int E) {
    int e = blockIdx.x * blockDim.x + threadIdx.x;
    if (e >= E) return;
    int s, d;
    get_edge(ei, e, E, g_is64, s, d);
    atomicAdd(&g_deg[d], 1);
}

// ---------------- hierarchical scan -----------------------------------------
__global__ __launch_bounds__(256) void scan1_kernel(int M) {
    __shared__ int red[8];
    int i = blockIdx.x * 256 + threadIdx.x;
    int d = (i < M) ? g_deg[i] : 0;
    if (i < M) g_dinv[i] = rsqrtf((float)(d + 1));
    int v = d;
    #pragma unroll
    for (int off = 16; off > 0; off >>= 1) v += __shfl_down_sync(0xffffffffu, v, off);
    if ((threadIdx.x & 31) == 0) red[threadIdx.x >> 5] = v;
    __syncthreads();
    if (threadIdx.x < 8) {
        int s = red[threadIdx.x];
        #pragma unroll
        for (int off = 4; off > 0; off >>= 1) s += __shfl_down_sync(0xffu, s, off);
        if (threadIdx.x == 0) g_bsum[blockIdx.x] = s;
    }
}

__global__ __launch_bounds__(256) void scan2_kernel() {
    __shared__ int sm[256];
    int t = threadIdx.x;
    sm[t] = (t < SCAN_B) ? g_bsum[t] : 0;
    __syncthreads();
    #pragma unroll
    for (int off = 1; off < 256; off <<= 1) {
        int v = (t >= off) ? sm[t - off] : 0;
        __syncthreads();
        sm[t] += v;
        __syncthreads();
    }
    if (t < SCAN_B) g_boff[t] = (t > 0) ? sm[t - 1] : 0;
}

__global__ __launch_bounds__(256) void scan3_kernel(int M, int E) {
    __shared__ int sm[256];
    int t = threadIdx.x;
    int i = blockIdx.x * 256 + t;
    int d = (i < M) ? g_deg[i] : 0;
    sm[t] = d;
    __syncthreads();
    #pragma unroll
    for (int off = 1; off < 256; off <<= 1) {
        int v = (t >= off) ? sm[t - off] : 0;
        __syncthreads();
        sm[t] += v;
        __syncthreads();
    }
    if (i < M) {
        int rs = g_boff[blockIdx.x] + sm[t] - d;
        g_row_start[i] = rs;
        g_cursor[i]    = rs;
    }
    if (i == M - 1) g_row_start[M] = E;
}

__global__ void fill_kernel(const void* __restrict__ ei, int E) {
    int e = blockIdx.x * blockDim.x + threadIdx.x;
    if (e >= E) return;
    int s, d;
    get_edge(ei, e, E, g_is64, s, d);
    int pos = atomicAdd(&g_cursor[d], 1);
    g_src[pos] = s;
}

// ---------------- GEMM1 (TF32, cp.async double-buffered): f1h = X @ W1 ------
#define NT1 (IN_C / 16)
__global__ __launch_bounds__(256, 2) void gemm1_kernel(
    const float* __restrict__ A, const float* __restrict__ W, int M) {
    __shared__ union {
        struct { float As[2][128][20]; float Bs[2][16][136]; } p;
        float stage[128 * 64];
    } sm;
    int tid = threadIdx.x;
    int wid = tid >> 5;
    int wm = wid & 3;
    int wn = wid >> 2;
    int bm = blockIdx.x * 128;

    wmma::fragment<wmma::accumulator, 16, 16, 8, float> c[2][4];
    #pragma unroll
    for (int i = 0; i < 2; i++)
        #pragma unroll
        for (int j = 0; j < 4; j++) wmma::fill_fragment(c[i][j], 0.f);

    auto issue = [&](int kt, int buf) {
        int k0 = kt * 16;
        #pragma unroll
        for (int i = 0; i < 2; ++i) {
            int idx = tid * 2 + i;
            int r = idx >> 2, c4 = (idx & 3) * 4;
            int gm = bm + r;
            int gmc = (gm < M) ? gm : (M - 1);
            cp16(&sm.p.As[buf][r][c4], &A[(size_t)gmc * IN_C + k0 + c4],
                 (gm < M) ? 16 : 0);
        }
        #pragma unroll
        for (int i = 0; i < 2; ++i) {
            int idx = tid * 2 + i;
            int kk = idx >> 5, n4 = (idx & 31) * 4;
            cp16(&sm.p.Bs[buf][kk][n4], &W[(size_t)(k0 + kk) * HID_C + n4], 16);
        }
        CP_COMMIT();
    };

    auto compute = [&](int buf) {
        #pragma unroll
        for (int ks = 0; ks < 16; ks += 8) {
            wmma::fragment<wmma::matrix_a, 16, 16, 8, wmma::precision::tf32, wmma::row_major> a[2];
            wmma::fragment<wmma::matrix_b, 16, 16, 8, wmma::precision::tf32, wmma::row_major> b[4];
            #pragma unroll
            for (int i = 0; i < 2; i++) {
                wmma::load_matrix_sync(a[i], &sm.p.As[buf][wm * 32 + i * 16][ks], 20);
                #pragma unroll
                for (int t = 0; t < a[i].num_elements; t++)
                    a[i].x[t] = wmma::__float_to_tf32(a[i].x[t]);
            }
            #pragma unroll
            for (int j = 0; j < 4; j++) {
                wmma::load_matrix_sync(b[j], &sm.p.Bs[buf][ks][wn * 64 + j * 16], 136);
                #pragma unroll
                for (int t = 0; t < b[j].num_elements; t++)
                    b[j].x[t] = wmma::__float_to_tf32(b[j].x[t]);
            }
            #pragma unroll
            for (int i = 0; i < 2; i++)
                #pragma unroll
                for (int j = 0; j < 4; j++)
                    wmma::mma_sync(c[i][j], a[i], b[j], c[i][j]);
        }
    };

    issue(0, 0);
    for (int t = 0; t < NT1; ++t) {
        if (t + 1 < NT1) {
            issue(t + 1, (t + 1) & 1);
            CP_WAIT1();
        } else {
            CP_WAIT0();
        }
        __syncthreads();
        compute(t & 1);
        __syncthreads();
    }

    // Epilogue: stage each 64-wide half in smem, emit half2 to g_f1h.
    #pragma unroll
    for (int half = 0; half < 2; ++half) {
        if (wn == half) {
            #pragma unroll
            for (int i = 0; i < 2; i++)
                #pragma unroll
                for (int j = 0; j < 4; j++)
                    wmma::store_matrix_sync(&sm.stage[(wm * 32 + i * 16) * 64 + j * 16],
                                            c[i][j], 64, wmma::mem_row_major);
        }
        __syncthreads();
        #pragma unroll
        for (int it = 0; it < 16; ++it) {
            int idx = tid + it * 256;     // 0..4095 half2 slots (128 rows x 32)
            int r  = idx >> 5;
            int cp = idx & 31;
            int gm = bm + r;
            if (gm < M) {
                float2 f = *(float2*)&sm.stage[r * 64 + cp * 2];
                *(__half2*)&g_f1h[(size_t)gm * HID_C + half * 64 + cp * 2] =
                    __float22half2_rn(f);
            }
        }
        __syncthreads();
    }
}

// ---------------- gather layer 1 (warp per node), fp16 messages, fused b1/relu
__global__ __launch_bounds__(256) void gather1_kernel(const float* __restrict__ b1, int M) {
    int w    = (blockIdx.x * blockDim.x + threadIdx.x) >> 5;
    int lane = threadIdx.x & 31;
    if (w >= M) return;
    int start = g_row_start[w];
    int end   = g_row_start[w + 1];
    float dn = g_dinv[w];

    float ax, ay, az, aw;
    {   // self-loop seed
        uint2 u = __ldg((const uint2*)&g_f1h[(size_t)w * HID_C] + lane);
        float2 f0 = __half22float2(*(__half2*)&u.x);
        float2 f1 = __half22float2(*(__half2*)&u.y);
        ax = f0.x * dn; ay = f0.y * dn; az = f1.x * dn; aw = f1.y * dn;
    }

    int i = start;
    for (; i + 4 <= end; i += 4) {
        int s0 = g_src[i], s1 = g_src[i + 1], s2 = g_src[i + 2], s3 = g_src[i + 3];
        float d0 = g_dinv[s0], d1 = g_dinv[s1], d2 = g_dinv[s2], d3 = g_dinv[s3];
        uint2 u0 = __ldg((const uint2*)&g_f1h[(size_t)s0 * HID_C] + lane);
        uint2 u1 = __ldg((const uint2*)&g_f1h[(size_t)s1 * HID_C] + lane);
        uint2 u2 = __ldg((const uint2*)&g_f1h[(size_t)s2 * HID_C] + lane);
        uint2 u3 = __ldg((const uint2*)&g_f1h[(size_t)s3 * HID_C] + lane);
        float2 p0 = __half22float2(*(__half2*)&u0.x), q0 = __half22float2(*(__half2*)&u0.y);
        float2 p1 = __half22float2(*(__half2*)&u1.x), q1 = __half22float2(*(__half2*)&u1.y);
        float2 p2 = __half22float2(*(__half2*)&u2.x), q2 = __half22float2(*(__half2*)&u2.y);
        float2 p3 = __half22float2(*(__half2*)&u3.x), q3 = __half22float2(*(__half2*)&u3.y);
        ax += p0.x * d0 + p1.x * d1 + p2.x * d2 + p3.x * d3;
        ay += p0.y * d0 + p1.y * d1 + p2.y * d2 + p3.y * d3;
        az += q0.x * d0 + q1.x * d1 + q2.x * d2 + q3.x * d3;
        aw += q0.y * d0 + q1.y * d1 + q2.y * d2 + q3.y * d3;
    }
    for (; i < end; ++i) {
        int s = g_src[i];
        float ds = g_dinv[s];
        uint2 u = __ldg((const uint2*)&g_f1h[(size_t)s * HID_C] + lane);
        float2 p = __half22float2(*(__half2*)&u.x);
        float2 q = __half22float2(*(__half2*)&u.y);
        ax += p.x * ds; ay += p.y * ds; az += q.x * ds; aw += q.y * ds;
    }
    float4 bb = __ldg((const float4*)b1 + lane);
    float4 r;
    r.x = fmaxf(fmaf(ax, dn, bb.x), 0.f);
    r.y = fmaxf(fmaf(ay, dn, bb.y), 0.f);
    r.z = fmaxf(fmaf(az, dn, bb.z), 0.f);
    r.w = fmaxf(fmaf(aw, dn, bb.w), 0.f);
    *((float4*)&g_a1[(size_t)w * HID_C] + lane) = r;
}

// ---------------- GEMM2 (TF32, cp.async double-buffered): f2h = a1 @ W2 -----
#define NT2 (HID_C / 16)
__global__ __launch_bounds__(256, 2) void gemm2_kernel(
    const float* __restrict__ W, int M) {
    __shared__ union {
        struct { float As[2][128][20]; float Bs[2][16][72]; } p;
        float stage[128 * 64];
    } sm;
    int tid = threadIdx.x;
    int wid = tid >> 5;
    int wm = wid & 3;
    int wn = wid >> 2;
    int bm = blockIdx.x * 128;

    wmma::fragment<wmma::accumulator, 16, 16, 8, float> c[2][2];
    #pragma unroll
    for (int i = 0; i < 2; i++)
        #pragma unroll
        for (int j = 0; j < 2; j++) wmma::fill_fragment(c[i][j], 0.f);

    auto issue = [&](int kt, int buf) {
        int k0 = kt * 16;
        #pragma unroll
        for (int i = 0; i < 2; ++i) {
            int idx = tid * 2 + i;
            int r = idx >> 2, c4 = (idx & 3) * 4;
            int gm = bm + r;
            int gmc = (gm < M) ? gm : (M - 1);
            cp16(&sm.p.As[buf][r][c4], &g_a1[(size_t)gmc * HID_C + k0 + c4],
                 (gm < M) ? 16 : 0);
        }
        {
            int kk = tid >> 4, n4 = (tid & 15) * 4;
            cp16(&sm.p.Bs[buf][kk][n4], &W[(size_t)(k0 + kk) * OUT_C + n4], 16);
        }
        CP_COMMIT();
    };

    auto compute = [&](int buf) {
        #pragma unroll
        for (int ks = 0; ks < 16; ks += 8) {
            wmma::fragment<wmma::matrix_a, 16, 16, 8, wmma::precision::tf32, wmma::row_major> a[2];
            wmma::fragment<wmma::matrix_b, 16, 16, 8, wmma::precision::tf32, wmma::row_major> b[2];
            #pragma unroll
            for (int i = 0; i < 2; i++) {
                wmma::load_matrix_sync(a[i], &sm.p.As[buf][wm * 32 + i * 16][ks], 20);
                #pragma unroll
                for (int t = 0; t < a[i].num_elements; t++)
                    a[i].x[t] = wmma::__float_to_tf32(a[i].x[t]);
            }
            #pragma unroll
            for (int j = 0; j < 2; j++) {
                wmma::load_matrix_sync(b[j], &sm.p.Bs[buf][ks][wn * 32 + j * 16], 72);
                #pragma unroll
                for (int t = 0; t < b[j].num_elements; t++)
                    b[j].x[t] = wmma::__float_to_tf32(b[j].x[t]);
            }
            #pragma unroll
            for (int i = 0; i < 2; i++)
                #pragma unroll
                for (int j = 0; j < 2; j++)
                    wmma::mma_sync(c[i][j], a[i], b[j], c[i][j]);
        }
    };

    issue(0, 0);
    for (int t = 0; t < NT2; ++t) {
        if (t + 1 < NT2) {
            issue(t + 1, (t + 1) & 1);
            CP_WAIT1();
        } else {
            CP_WAIT0();
        }
        __syncthreads();
        compute(t & 1);
        __syncthreads();
    }

    // Epilogue: stage full 128x64 tile, emit half2 to g_f2h.
    #pragma unroll
    for (int i = 0; i < 2; i++)
        #pragma unroll
        for (int j = 0; j < 2; j++)
            wmma::store_matrix_sync(&sm.stage[(wm * 32 + i * 16) * 64 + wn * 32 + j * 16],
                                    c[i][j], 64, wmma::mem_row_major);
    __syncthreads();
    #pragma unroll
    for (int it = 0; it < 16; ++it) {
        int idx = tid + it * 256;     // 0..4095 half2 slots (128 rows x 32)
        int r  = idx >> 5;
        int cp = idx & 31;
        int gm = bm + r;
        if (gm < M) {
            float2 f = *(float2*)&sm.stage[r * 64 + cp * 2];
            *(__half2*)&g_f2h[(size_t)gm * OUT_C + cp * 2] = __float22half2_rn(f);
        }
    }
}

// ---------------- gather layer 2 + bias (16 lanes per node), fp16 messages --
__global__ __launch_bounds__(256) void gather2_kernel(
    float* __restrict__ out, const float* __restrict__ b2, int M) {
    int t    = blockIdx.x * blockDim.x + threadIdx.x;
    int n    = t >> 4;
    int lane = t & 15;
    if (n >= M) return;
    int start = g_row_start[n];
    int end   = g_row_start[n + 1];
    float dn = g_dinv[n];

    float ax, ay, az, aw;
    {
        uint2 u = __ldg((const uint2*)&g_f2h[(size_t)n * OUT_C] + lane);
        float2 f0 = __half22float2(*(__half2*)&u.x);
        float2 f1 = __half22float2(*(__half2*)&u.y);
        ax = f0.x * dn; ay = f0.y * dn; az = f1.x * dn; aw = f1.y * dn;
    }

    int i = start;
    for (; i + 4 <= end; i += 4) {
        int s0 = g_src[i], s1 = g_src[i + 1], s2 = g_src[i + 2], s3 = g_src[i + 3];
        float d0 = g_dinv[s0], d1 = g_dinv[s1], d2 = g_dinv[s2], d3 = g_dinv[s3];
        uint2 u0 = __ldg((const uint2*)&g_f2h[(size_t)s0 * OUT_C] + lane);
        uint2 u1 = __ldg((const uint2*)&g_f2h[(size_t)s1 * OUT_C] + lane);
        uint2 u2 = __ldg((const uint2*)&g_f2h[(size_t)s2 * OUT_C] + lane);
        uint2 u3 = __ldg((const uint2*)&g_f2h[(size_t)s3 * OUT_C] + lane);
        float2 p0 = __half22float2(*(__half2*)&u0.x), q0 = __half22float2(*(__half2*)&u0.y);
        float2 p1 = __half22float2(*(__half2*)&u1.x), q1 = __half22float2(*(__half2*)&u1.y);
        float2 p2 = __half22float2(*(__half2*)&u2.x), q2 = __half22float2(*(__half2*)&u2.y);
        float2 p3 = __half22float2(*(__half2*)&u3.x), q3 = __half22float2(*(__half2*)&u3.y);
        ax += p0.x * d0 + p1.x * d1 + p2.x * d2 + p3.x * d3;
        ay += p0.y * d0 + p1.y * d1 + p2.y * d2 + p3.y * d3;
        az += q0.x * d0 + q1.x * d1 + q2.x * d2 + q3.x * d3;
        aw += q0.y * d0 + q1.y * d1 + q2.y * d2 + q3.y * d3;
    }
    for (; i < end; ++i) {
        int s = g_src[i];
        float ds = g_dinv[s];
        uint2 u = __ldg((const uint2*)&g_f2h[(size_t)s * OUT_C] + lane);
        float2 p = __half22float2(*(__half2*)&u.x);
        float2 q = __half22float2(*(__half2*)&u.y);
        ax += p.x * ds; ay += p.y * ds; az += q.x * ds; aw += q.y * ds;
    }
    float4 bb = __ldg((const float4*)b2 + lane);
    float4 r;
    r.x = ax * dn + bb.x; r.y = ay * dn + bb.y;
    r.z = az * dn + bb.z; r.w = aw * dn + bb.w;
    *((float4*)&out[(size_t)n * OUT_C] + lane) = r;
}

// ---------------- launch ----------------------------------------------------
extern "C" void kernel_launch(void* const* d_in, const int* in_sizes, int n_in,
                              void* d_out, int out_size) {
    const float* features = (const float*)d_in[0];
    const void*  edge_idx = d_in[1];
    const float* W1 = (const float*)d_in[2];
    const float* b1 = (const float*)d_in[3];
    const float* W2 = (const float*)d_in[4];
    const float* b2 = (const float*)d_in[5];
    float* out = (float*)d_out;

    int M = in_sizes[0] / IN_C;       // 50000
    int E = in_sizes[1] / 2;          // 800000

    int gblocks = (M + 127) / 128;    // 391

    // Fork: gemm1 (independent of graph preprocessing) on side stream.
    cudaEventRecord(g_ss.ev_fork, 0);
    cudaStreamWaitEvent(g_ss.s2, g_ss.ev_fork, 0);
    gemm1_kernel<<<gblocks, 256, 0, g_ss.s2>>>(features, W1, M);
    cudaEventRecord(g_ss.ev_join, g_ss.s2);

    // Preprocessing chain on the main (capture) stream, concurrent with gemm1.
    prep_kernel<<<(M + 255) / 256, 256>>>((const long long*)edge_idx, E, M);
    count_deg_kernel<<<(E + 255) / 256, 256>>>(edge_idx, E);
    scan1_kernel<<<SCAN_B, 256>>>(M);
    scan2_kernel<<<1, 256>>>();
    scan3_kernel<<<SCAN_B, 256>>>(M, E);
    fill_kernel<<<(E + 255) / 256, 256>>>(edge_idx, E);

    // Join: gather1 needs both gemm1 output and the CSR.
    cudaStreamWaitEvent(0, g_ss.ev_join, 0);

    long long t1 = (long long)M * 32;
    gather1_kernel<<<(unsigned)((t1 + 255) / 256), 256>>>(b1, M);

    gemm2_kernel<<<gblocks, 256>>>(W2, M);

    long long t2 = (long long)M * 16;
    gather2_kernel<<<(unsigned)((t2 + 255) / 256), 256>>>(out, b2, M);
}

// round 10
// speedup vs baseline: 1.5983x; 1.2542x over previous
#include <cuda_runtime.h>
#include <cuda_fp16.h>
#include <mma.h>
#include <cstdint>

using namespace nvcuda;

#define NODES_MAX 50000
#define PAD_M     50176      // 392*128, pad for unguarded wmma stores
#define E_MAX     1000000
#define IN_C  256
#define HID_C 128
#define OUT_C 64

#define SCAN_B    196        // scan blocks: 196*256 = 50176 >= NODES_MAX

// ---------------- scratch ----------------------------------------------------
__device__ __half g_xh [NODES_MAX * IN_C];   // features, fp16
__device__ __half g_w1h[IN_C * HID_C];       // W1, fp16
__device__ __half g_w2h[HID_C * OUT_C];      // W2, fp16
__device__ __half g_f1h[PAD_M * HID_C];      // gemm1 output (X@W1), fp16 messages
__device__ __half g_a1h[NODES_MAX * HID_C];  // relu(agg1 + b1), fp16 (gemm2 A)
__device__ __half g_f2h[PAD_M * OUT_C];      // gemm2 output, fp16 messages
__device__ float  g_dinv[NODES_MAX];
__device__ int    g_deg [NODES_MAX];
__device__ int    g_row_start[NODES_MAX + 1];
__device__ int    g_cursor[NODES_MAX];
__device__ int    g_src[E_MAX];              // CSR-by-dst: source node per slot
__device__ int    g_bsum[SCAN_B];
__device__ int    g_boff[SCAN_B];
__device__ int    g_is64;

// ---------------- side stream for graph-fork (created at static init) -------
namespace {
struct SideStream {
    cudaStream_t s2 = nullptr;
    cudaEvent_t  ev_fork = nullptr, ev_join = nullptr;
    SideStream() {
        cudaStreamCreateWithFlags(&s2, cudaStreamNonBlocking);
        cudaEventCreateWithFlags(&ev_fork, cudaEventDisableTiming);
        cudaEventCreateWithFlags(&ev_join, cudaEventDisableTiming);
    }
};
SideStream g_ss;
}

// ---------------- cp.async helpers ------------------------------------------
__device__ __forceinline__ void cp16(void* smem, const void* gsrc, int szbytes) {
    uint32_t sa = (uint32_t)__cvta_generic_to_shared(smem);
    asm volatile("cp.async.cg.shared.global [%0], [%1], 16, %2;"
                 :: "r"(sa), "l"(gsrc), "r"(szbytes));
}
#define CP_COMMIT()  asm volatile("cp.async.commit_group;" ::: "memory")
#define CP_WAIT1()   asm volatile("cp.async.wait_group 1;" ::: "memory")
#define CP_WAIT0()   asm volatile("cp.async.wait_group 0;" ::: "memory")

// ---------------- fp32 -> fp16 conversion (X, W1, W2), 8 floats/thread ------
__global__ __launch_bounds__(256) void convert_kernel(
    const float* __restrict__ X, const float* __restrict__ W1,
    const float* __restrict__ W2, int M) {
    int i = blockIdx.x * blockDim.x + threadIdx.x;
    int nx  = M * IN_C / 8;
    int nw1 = IN_C * HID_C / 8;
    int nw2 = HID_C * OUT_C / 8;
    const float* src; __half* dst; int base;
    if (i < nx)            { src = X;  dst = g_xh;  base = i; }
    else if (i < nx + nw1) { src = W1; dst = g_w1h; base = i - nx; }
    else if (i < nx + nw1 + nw2) { src = W2; dst = g_w2h; base = i - nx - nw1; }
    else return;
    float4 a = ((const float4*)src)[base * 2];
    float4 b = ((const float4*)src)[base * 2 + 1];
    __half2 h0 = __floats2half2_rn(a.x, a.y);
    __half2 h1 = __floats2half2_rn(a.z, a.w);
    __half2 h2 = __floats2half2_rn(b.x, b.y);
    __half2 h3 = __floats2half2_rn(b.z, b.w);
    uint4 u;
    u.x = *(uint32_t*)&h0; u.y = *(uint32_t*)&h1;
    u.z = *(uint32_t*)&h2; u.w = *(uint32_t*)&h3;
    ((uint4*)dst)[base] = u;
}

// ---------------- prep: zero deg + dtype detect ------------------------------
__global__ void prep_kernel(const long long* __restrict__ p, int E, int M) {
    int i = blockIdx.x * blockDim.x + threadIdx.x;
    if (i < M) g_deg[i] = 0;
    if (blockIdx.x == 0) {
        __shared__ int bad;
        if (threadIdx.x == 0) bad = 0;
        __syncthreads();
        if ((int)threadIdx.x < 256 && (int)threadIdx.x < E) {
            long long v = p[threadIdx.x];
            if (v < 0 || v >= (long long)M) bad = 1;
        }
        __syncthreads();
        if (threadIdx.x == 0) g_is64 = bad ? 0 : 1;
    }
}

__device__ __forceinline__ void get_edge(const void* ei, int e, int E, int is64,
                                         int& s, int& d) {
    if (is64) {
        const long long* p = (const long long*)ei;
        s = (int)p[e]; d = (int)p[E + e];
    } else {
        const int* p = (const int*)ei;
        s = p[e]; d = p[E + e];
    }
}

__global__ void count_deg_kernel(const void* __restrict__ ei, int E) {
    int e = blockIdx.x * blockDim.x + threadIdx.x;
    if (e >= E) return;
    int s, d;
    get_edge(ei, e, E, g_is64, s, d);
    atomicAdd(&g_deg[d], 1);
}

// ---------------- hierarchical scan -----------------------------------------
__global__ __launch_bounds__(256) void scan1_kernel(int M) {
    __shared__ int red[8];
    int i = blockIdx.x * 256 + threadIdx.x;
    int d = (i < M) ? g_deg[i] : 0;
    if (i < M) g_dinv[i] = rsqrtf((float)(d + 1));
    int v = d;
    #pragma unroll
    for (int off = 16; off > 0; off >>= 1) v += __shfl_down_sync(0xffffffffu, v, off);
    if ((threadIdx.x & 31) == 0) red[threadIdx.x >> 5] = v;
    __syncthreads();
    if (threadIdx.x < 8) {
        int s = red[threadIdx.x];
        #pragma unroll
        for (int off = 4; off > 0; off >>= 1) s += __shfl_down_sync(0xffu, s, off);
        if (threadIdx.x == 0) g_bsum[blockIdx.x] = s;
    }
}

__global__ __launch_bounds__(256) void scan2_kernel() {
    __shared__ int sm[256];
    int t = threadIdx.x;
    sm[t] = (t < SCAN_B) ? g_bsum[t] : 0;
    __syncthreads();
    #pragma unroll
    for (int off = 1; off < 256; off <<= 1) {
        int v = (t >= off) ? sm[t - off] : 0;
        __syncthreads();
        sm[t] += v;
        __syncthreads();
    }
    if (t < SCAN_B) g_boff[t] = (t > 0) ? sm[t - 1] : 0;
}

__global__ __launch_bounds__(256) void scan3_kernel(int M, int E) {
    __shared__ int sm[256];
    int t = threadIdx.x;
    int i = blockIdx.x * 256 + t;
    int d = (i < M) ? g_deg[i] : 0;
    sm[t] = d;
    __syncthreads();
    #pragma unroll
    for (int off = 1; off < 256; off <<= 1) {
        int v = (t >= off) ? sm[t - off] : 0;
        __syncthreads();
        sm[t] += v;
        __syncthreads();
    }
    if (i < M) {
        int rs = g_boff[blockIdx.x] + sm[t] - d;
        g_row_start[i] = rs;
        g_cursor[i]    = rs;
    }
    if (i == M - 1) g_row_start[M] = E;
}

__global__ void fill_kernel(const void* __restrict__ ei, int E) {
    int e = blockIdx.x * blockDim.x + threadIdx.x;
    if (e >= E) return;
    int s, d;
    get_edge(ei, e, E, g_is64, s, d);
    int pos = atomicAdd(&g_cursor[d], 1);
    g_src[pos] = s;
}

// ---------------- GEMM1 (fp16 HMMA, cp.async double-buffered): f1h = Xh@W1h -
// BM=128 BN=128 BK=32, 8 warps, warp tile 32x64, m16n16k16, 8 k-tiles.
#define NT1 (IN_C / 32)
__global__ __launch_bounds__(256, 2) void gemm1_kernel(int M) {
    __shared__ union {
        struct { __half As[2][128][40]; __half Bs[2][32][136]; } p;
        float stage[128 * 64];
    } sm;
    int tid = threadIdx.x;
    int wid = tid >> 5;
    int wm = wid & 3;
    int wn = wid >> 2;
    int bm = blockIdx.x * 128;

    wmma::fragment<wmma::accumulator, 16, 16, 16, float> c[2][4];
    #pragma unroll
    for (int i = 0; i < 2; i++)
        #pragma unroll
        for (int j = 0; j < 4; j++) wmma::fill_fragment(c[i][j], 0.f);

    auto issue = [&](int kt, int buf) {
        int k0 = kt * 32;
        // A: 128 rows x 32 halves (64B/row = 4 chunks), 512 chunks, 2/thread
        #pragma unroll
        for (int i = 0; i < 2; ++i) {
            int idx = tid * 2 + i;
            int r = idx >> 2, c8 = (idx & 3) * 8;
            int gm = bm + r;
            int gmc = (gm < M) ? gm : (M - 1);
            cp16(&sm.p.As[buf][r][c8], &g_xh[(size_t)gmc * IN_C + k0 + c8],
                 (gm < M) ? 16 : 0);
        }
        // B: 32 k-rows x 128 halves (256B/row = 16 chunks), 512 chunks, 2/thread
        #pragma unroll
        for (int i = 0; i < 2; ++i) {
            int idx = tid * 2 + i;
            int kk = idx >> 4, n8 = (idx & 15) * 8;
            cp16(&sm.p.Bs[buf][kk][n8], &g_w1h[(size_t)(k0 + kk) * HID_C + n8], 16);
        }
        CP_COMMIT();
    };

    auto compute = [&](int buf) {
        #pragma unroll
        for (int ks = 0; ks < 32; ks += 16) {
            wmma::fragment<wmma::matrix_a, 16, 16, 16, __half, wmma::row_major> a[2];
            wmma::fragment<wmma::matrix_b, 16, 16, 16, __half, wmma::row_major> b[4];
            #pragma unroll
            for (int i = 0; i < 2; i++)
                wmma::load_matrix_sync(a[i], &sm.p.As[buf][wm * 32 + i * 16][ks], 40);
            #pragma unroll
            for (int j = 0; j < 4; j++)
                wmma::load_matrix_sync(b[j], &sm.p.Bs[buf][ks][wn * 64 + j * 16], 136);
            #pragma unroll
            for (int i = 0; i < 2; i++)
                #pragma unroll
                for (int j = 0; j < 4; j++)
                    wmma::mma_sync(c[i][j], a[i], b[j], c[i][j]);
        }
    };

    issue(0, 0);
    for (int t = 0; t < NT1; ++t) {
        if (t + 1 < NT1) {
            issue(t + 1, (t + 1) & 1);
            CP_WAIT1();
        } else {
            CP_WAIT0();
        }
        __syncthreads();
        compute(t & 1);
        __syncthreads();
    }

    // Epilogue: stage each 64-wide half of the tile, emit half2 to g_f1h.
    #pragma unroll
    for (int half = 0; half < 2; ++half) {
        if (wn == half) {
            #pragma unroll
            for (int i = 0; i < 2; i++)
                #pragma unroll
                for (int j = 0; j < 4; j++)
                    wmma::store_matrix_sync(&sm.stage[(wm * 32 + i * 16) * 64 + j * 16],
                                            c[i][j], 64, wmma::mem_row_major);
        }
        __syncthreads();
        #pragma unroll
        for (int it = 0; it < 16; ++it) {
            int idx = tid + it * 256;     // 0..4095 half2 slots (128 rows x 32)
            int r  = idx >> 5;
            int cp = idx & 31;
            int gm = bm + r;
            if (gm < M) {
                float2 f = *(float2*)&sm.stage[r * 64 + cp * 2];
                *(__half2*)&g_f1h[(size_t)gm * HID_C + half * 64 + cp * 2] =
                    __float22half2_rn(f);
            }
        }
        __syncthreads();
    }
}

// ---------------- gather layer 1 (warp per node), fp16 in, fp16 out ---------
__global__ __launch_bounds__(256) void gather1_kernel(const float* __restrict__ b1, int M) {
    int w    = (blockIdx.x * blockDim.x + threadIdx.x) >> 5;
    int lane = threadIdx.x & 31;
    if (w >= M) return;
    int start = g_row_start[w];
    int end   = g_row_start[w + 1];
    float dn = g_dinv[w];

    float ax, ay, az, aw;
    {   // self-loop seed
        uint2 u = __ldg((const uint2*)&g_f1h[(size_t)w * HID_C] + lane);
        float2 f0 = __half22float2(*(__half2*)&u.x);
        float2 f1 = __half22float2(*(__half2*)&u.y);
        ax = f0.x * dn; ay = f0.y * dn; az = f1.x * dn; aw = f1.y * dn;
    }

    int i = start;
    for (; i + 4 <= end; i += 4) {
        int s0 = g_src[i], s1 = g_src[i + 1], s2 = g_src[i + 2], s3 = g_src[i + 3];
        float d0 = g_dinv[s0], d1 = g_dinv[s1], d2 = g_dinv[s2], d3 = g_dinv[s3];
        uint2 u0 = __ldg((const uint2*)&g_f1h[(size_t)s0 * HID_C] + lane);
        uint2 u1 = __ldg((const uint2*)&g_f1h[(size_t)s1 * HID_C] + lane);
        uint2 u2 = __ldg((const uint2*)&g_f1h[(size_t)s2 * HID_C] + lane);
        uint2 u3 = __ldg((const uint2*)&g_f1h[(size_t)s3 * HID_C] + lane);
        float2 p0 = __half22float2(*(__half2*)&u0.x), q0 = __half22float2(*(__half2*)&u0.y);
        float2 p1 = __half22float2(*(__half2*)&u1.x), q1 = __half22float2(*(__half2*)&u1.y);
        float2 p2 = __half22float2(*(__half2*)&u2.x), q2 = __half22float2(*(__half2*)&u2.y);
        float2 p3 = __half22float2(*(__half2*)&u3.x), q3 = __half22float2(*(__half2*)&u3.y);
        ax += p0.x * d0 + p1.x * d1 + p2.x * d2 + p3.x * d3;
        ay += p0.y * d0 + p1.y * d1 + p2.y * d2 + p3.y * d3;
        az += q0.x * d0 + q1.x * d1 + q2.x * d2 + q3.x * d3;
        aw += q0.y * d0 + q1.y * d1 + q2.y * d2 + q3.y * d3;
    }
    for (; i < end; ++i) {
        int s = g_src[i];
        float ds = g_dinv[s];
        uint2 u = __ldg((const uint2*)&g_f1h[(size_t)s * HID_C] + lane);
        float2 p = __half22float2(*(__half2*)&u.x);
        float2 q = __half22float2(*(__half2*)&u.y);
        ax += p.x * ds; ay += p.y * ds; az += q.x * ds; aw += q.y * ds;
    }
    float4 bb = __ldg((const float4*)b1 + lane);
    __half2 h0 = __floats2half2_rn(fmaxf(fmaf(ax, dn, bb.x), 0.f),
                                   fmaxf(fmaf(ay, dn, bb.y), 0.f));
    __half2 h1 = __floats2half2_rn(fmaxf(fmaf(az, dn, bb.z), 0.f),
                                   fmaxf(fmaf(aw, dn, bb.w), 0.f));
    uint2 u;
    u.x = *(uint32_t*)&h0; u.y = *(uint32_t*)&h1;
    ((uint2*)&g_a1h[(size_t)w * HID_C])[lane] = u;
}

// ---------------- GEMM2 (fp16 HMMA, cp.async double-buffered): f2h = a1h@W2h
// BM=128 BN=64 BK=32, 8 warps, warp tile 32x32, 4 k-tiles.
#define NT2 (HID_C / 32)
__global__ __launch_bounds__(256, 2) void gemm2_kernel(int M) {
    __shared__ union {
        struct { __half As[2][128][40]; __half Bs[2][32][72]; } p;
        float stage[128 * 64];
    } sm;
    int tid = threadIdx.x;
    int wid = tid >> 5;
    int wm = wid & 3;
    int wn = wid >> 2;
    int bm = blockIdx.x * 128;

    wmma::fragment<wmma::accumulator, 16, 16, 16, float> c[2][2];
    #pragma unroll
    for (int i = 0; i < 2; i++)
        #pragma unroll
        for (int j = 0; j < 2; j++) wmma::fill_fragment(c[i][j], 0.f);

    auto issue = [&](int kt, int buf) {
        int k0 = kt * 32;
        #pragma unroll
        for (int i = 0; i < 2; ++i) {
            int idx = tid * 2 + i;
            int r = idx >> 2, c8 = (idx & 3) * 8;
            int gm = bm + r;
            int gmc = (gm < M) ? gm : (M - 1);
            cp16(&sm.p.As[buf][r][c8], &g_a1h[(size_t)gmc * HID_C + k0 + c8],
                 (gm < M) ? 16 : 0);
        }
        {   // B: 32 k-rows x 64 halves (128B/row = 8 chunks), 256 chunks, 1/thread
            int kk = tid >> 3, n8 = (tid & 7) * 8;
            cp16(&sm.p.Bs[buf][kk][n8], &g_w2h[(size_t)(k0 + kk) * OUT_C + n8], 16);
        }
        CP_COMMIT();
    };

    auto compute = [&](int buf) {
        #pragma unroll
        for (int ks = 0; ks < 32; ks += 16) {
            wmma::fragment<wmma::matrix_a, 16, 16, 16, __half, wmma::row_major> a[2];
            wmma::fragment<wmma::matrix_b, 16, 16, 16, __half, wmma::row_major> b[2];
            #pragma unroll
            for (int i = 0; i < 2; i++)
                wmma::load_matrix_sync(a[i], &sm.p.As[buf][wm * 32 + i * 16][ks], 40);
            #pragma unroll
            for (int j = 0; j < 2; j++)
                wmma::load_matrix_sync(b[j], &sm.p.Bs[buf][ks][wn * 32 + j * 16], 72);
            #pragma unroll
            for (int i = 0; i < 2; i++)
                #pragma unroll
                for (int j = 0; j < 2; j++)
                    wmma::mma_sync(c[i][j], a[i], b[j], c[i][j]);
        }
    };

    issue(0, 0);
    for (int t = 0; t < NT2; ++t) {
        if (t + 1 < NT2) {
            issue(t + 1, (t + 1) & 1);
            CP_WAIT1();
        } else {
            CP_WAIT0();
        }
        __syncthreads();
        compute(t & 1);
        __syncthreads();
    }

    // Epilogue: stage full 128x64 tile, emit half2 to g_f2h.
    #pragma unroll
    for (int i = 0; i < 2; i++)
        #pragma unroll
        for (int j = 0; j < 2; j++)
            wmma::store_matrix_sync(&sm.stage[(wm * 32 + i * 16) * 64 + wn * 32 + j * 16],
                                    c[i][j], 64, wmma::mem_row_major);
    __syncthreads();
    #pragma unroll
    for (int it = 0; it < 16; ++it) {
        int idx = tid + it * 256;     // 0..4095 half2 slots (128 rows x 32)
        int r  = idx >> 5;
        int cp = idx & 31;
        int gm = bm + r;
        if (gm < M) {
            float2 f = *(float2*)&sm.stage[r * 64 + cp * 2];
            *(__half2*)&g_f2h[(size_t)gm * OUT_C + cp * 2] = __float22half2_rn(f);
        }
    }
}

// ---------------- gather layer 2 + bias (16 lanes per node), fp16 messages --
__global__ __launch_bounds__(256) void gather2_kernel(
    float* __restrict__ out, const float* __restrict__ b2, int M) {
    int t    = blockIdx.x * blockDim.x + threadIdx.x;
    int n    = t >> 4;
    int lane = t & 15;
    if (n >= M) return;
    int start = g_row_start[n];
    int end   = g_row_start[n + 1];
    float dn = g_dinv[n];

    float ax, ay, az, aw;
    {
        uint2 u = __ldg((const uint2*)&g_f2h[(size_t)n * OUT_C] + lane);
        float2 f0 = __half22float2(*(__half2*)&u.x);
        float2 f1 = __half22float2(*(__half2*)&u.y);
        ax = f0.x * dn; ay = f0.y * dn; az = f1.x * dn; aw = f1.y * dn;
    }

    int i = start;
    for (; i + 4 <= end; i += 4) {
        int s0 = g_src[i], s1 = g_src[i + 1], s2 = g_src[i + 2], s3 = g_src[i + 3];
        float d0 = g_dinv[s0], d1 = g_dinv[s1], d2 = g_dinv[s2], d3 = g_dinv[s3];
        uint2 u0 = __ldg((const uint2*)&g_f2h[(size_t)s0 * OUT_C] + lane);
        uint2 u1 = __ldg((const uint2*)&g_f2h[(size_t)s1 * OUT_C] + lane);
        uint2 u2 = __ldg((const uint2*)&g_f2h[(size_t)s2 * OUT_C] + lane);
        uint2 u3 = __ldg((const uint2*)&g_f2h[(size_t)s3 * OUT_C] + lane);
        float2 p0 = __half22float2(*(__half2*)&u0.x), q0 = __half22float2(*(__half2*)&u0.y);
        float2 p1 = __half22float2(*(__half2*)&u1.x), q1 = __half22float2(*(__half2*)&u1.y);
        float2 p2 = __half22float2(*(__half2*)&u2.x), q2 = __half22float2(*(__half2*)&u2.y);
        float2 p3 = __half22float2(*(__half2*)&u3.x), q3 = __half22float2(*(__half2*)&u3.y);
        ax += p0.x * d0 + p1.x * d1 + p2.x * d2 + p3.x * d3;
        ay += p0.y * d0 + p1.y * d1 + p2.y * d2 + p3.y * d3;
        az += q0.x * d0 + q1.x * d1 + q2.x * d2 + q3.x * d3;
        aw += q0.y * d0 + q1.y * d1 + q2.y * d2 + q3.y * d3;
    }
    for (; i < end; ++i) {
        int s = g_src[i];
        float ds = g_dinv[s];
        uint2 u = __ldg((const uint2*)&g_f2h[(size_t)s * OUT_C] + lane);
        float2 p = __half22float2(*(__half2*)&u.x);
        float2 q = __half22float2(*(__half2*)&u.y);
        ax += p.x * ds; ay += p.y * ds; az += q.x * ds; aw += q.y * ds;
    }
    float4 bb = __ldg((const float4*)b2 + lane);
    float4 r;
    r.x = ax * dn + bb.x; r.y = ay * dn + bb.y;
    r.z = az * dn + bb.z; r.w = aw * dn + bb.w;
    *((float4*)&out[(size_t)n * OUT_C] + lane) = r;
}

// ---------------- launch ----------------------------------------------------
extern "C" void kernel_launch(void* const* d_in, const int* in_sizes, int n_in,
                              void* d_out, int out_size) {
    const float* features = (const float*)d_in[0];
    const void*  edge_idx = d_in[1];
    const float* W1 = (const float*)d_in[2];
    const float* b1 = (const float*)d_in[3];
    const float* W2 = (const float*)d_in[4];
    const float* b2 = (const float*)d_in[5];
    float* out = (float*)d_out;

    int M = in_sizes[0] / IN_C;       // 50000
    int E = in_sizes[1] / 2;          // 800000

    int gblocks = (M + 127) / 128;    // 391

    // Fork: convert (X,W1,W2 -> fp16) + gemm1 on side stream, concurrent with
    // the CSR preprocessing chain on the main stream.
    cudaEventRecord(g_ss.ev_fork, 0);
    cudaStreamWaitEvent(g_ss.s2, g_ss.ev_fork, 0);
    {
        int total8 = (M * IN_C + IN_C * HID_C + HID_C * OUT_C) / 8;
        convert_kernel<<<(total8 + 255) / 256, 256, 0, g_ss.s2>>>(features, W1, W2, M);
    }
    gemm1_kernel<<<gblocks, 256, 0, g_ss.s2>>>(M);
    cudaEventRecord(g_ss.ev_join, g_ss.s2);

    // Preprocessing chain on the main (capture) stream.
    prep_kernel<<<(M + 255) / 256, 256>>>((const long long*)edge_idx, E, M);
    count_deg_kernel<<<(E + 255) / 256, 256>>>(edge_idx, E);
    scan1_kernel<<<SCAN_B, 256>>>(M);
    scan2_kernel<<<1, 256>>>();
    scan3_kernel<<<SCAN_B, 256>>>(M, E);
    fill_kernel<<<(E + 255) / 256, 256>>>(edge_idx, E);

    // Join: gather1 needs both gemm1 output and the CSR.
    cudaStreamWaitEvent(0, g_ss.ev_join, 0);

    long long t1 = (long long)M * 32;
    gather1_kernel<<<(unsigned)((t1 + 255) / 256), 256>>>(b1, M);

    gemm2_kernel<<<gblocks, 256>>>(M);

    long long t2 = (long long)M * 16;
    gather2_kernel<<<(unsigned)((t2 + 255) / 256), 256>>>(out, b2, M);
}